// round 2
// baseline (speedup 1.0000x reference)
#include <cuda_runtime.h>
#include <math.h>

// Problem constants
#define T_TOK 16384
#define H_DIM 1024
#define F_DIM 512
#define E_NUM 64
#define TOPK  2
#define TK    (T_TOK * TOPK)   // 32768 routed pairs

// GEMM tiling
#define BM 64
#define BN 64
#define BK 32
#define MAX_TILES (TK / BM + E_NUM)   // 576 upper bound on m-tiles

// -------------------- static device scratch (no runtime allocs) --------------------
__device__ int   g_count[E_NUM];
__device__ int   g_offset[E_NUM];
__device__ int   g_cursor[E_NUM];
__device__ int   g_pair_token[TK];
__device__ float g_pair_w[TK];
__device__ int   g_num_tiles;
__device__ int   g_tile_e[MAX_TILES];
__device__ int   g_tile_row[MAX_TILES];
__device__ int   g_tile_rows[MAX_TILES];
__device__ float g_act[(size_t)TK * F_DIM];   // 64 MB intermediate activations

// -------------------- routing --------------------
__global__ void k_init() {
    int i = threadIdx.x;
    if (i < E_NUM) g_count[i] = 0;
}

__global__ void k_count(const int* __restrict__ topk_ids) {
    int i = blockIdx.x * blockDim.x + threadIdx.x;
    if (i < TK) atomicAdd(&g_count[topk_ids[i]], 1);
}

__global__ void k_scan() {
    if (threadIdx.x == 0) {
        int off = 0, nt = 0;
        for (int e = 0; e < E_NUM; e++) {
            g_offset[e] = off;
            g_cursor[e] = 0;
            int c = g_count[e];
            for (int r = 0; r < c; r += BM) {
                g_tile_e[nt]    = e;
                g_tile_row[nt]  = off + r;
                g_tile_rows[nt] = (c - r < BM) ? (c - r) : BM;
                nt++;
            }
            off += c;
        }
        g_num_tiles = nt;
    }
}

__global__ void k_scatter(const int* __restrict__ topk_ids,
                          const float* __restrict__ topk_w) {
    int i = blockIdx.x * blockDim.x + threadIdx.x;
    if (i < TK) {
        int e   = topk_ids[i];
        int pos = g_offset[e] + atomicAdd(&g_cursor[e], 1);
        g_pair_token[pos] = i >> 1;        // token index (K=2)
        g_pair_w[pos]     = topk_w[i];
    }
}

// -------------------- swizzled transposed smem store --------------------
// Logical tile L[k][col], k in [0,32), col in [0,64). Physical:
//   P = k*64 + (((col>>2) ^ ((k>>2)&7)) << 2) + (col&3)
// Thread loads float4 along k (k = c0*4 .. c0*4+3), so (k>>2)&7 == c0 for all 4.
__device__ __forceinline__ void store_t(float* s, float4 v, int col, int c0) {
    int p = ((((col >> 2) ^ c0) << 2) | (col & 3));
    s[(c0 * 4 + 0) * 64 + p] = v.x;
    s[(c0 * 4 + 1) * 64 + p] = v.y;
    s[(c0 * 4 + 2) * 64 + p] = v.z;
    s[(c0 * 4 + 3) * 64 + p] = v.w;
}

// -------------------- GEMM1: act = silu(X @ Wg^T) * (X @ Wu^T) --------------------
// grid.x = F/BN (8) gate-column tiles (the matching up tile is computed in the
// same block); grid.y = MAX_TILES m-tiles.
__global__ void __launch_bounds__(256, 2)
k_gemm1(const float* __restrict__ hidden, const float* __restrict__ w_gu) {
    int tile = blockIdx.y;
    if (tile >= g_num_tiles) return;
    int e = g_tile_e[tile], row0 = g_tile_row[tile], rows = g_tile_rows[tile];
    int bx = blockIdx.x;

    __shared__ float sA [2][BK * BM];
    __shared__ float sBg[2][BK * BN];
    __shared__ float sBu[2][BK * BN];

    int tid = threadIdx.x;
    int r0 = tid >> 3;   // 0..31 : row within tile (also handles r0+32)
    int c0 = tid & 7;    // 0..7  : float4 column within 32-wide k slice
    int m0 = r0, m1 = r0 + 32;

    int t0 = g_pair_token[row0 + (m0 < rows ? m0 : 0)];
    int t1 = g_pair_token[row0 + (m1 < rows ? m1 : 0)];
    const float* A0 = hidden + (size_t)t0 * H_DIM + c0 * 4;
    const float* A1 = hidden + (size_t)t1 * H_DIM + c0 * 4;

    const float* Wg  = w_gu + (size_t)e * (2 * F_DIM) * H_DIM + (size_t)(bx * BN) * H_DIM;
    const float* Bg0 = Wg + (size_t)m0 * H_DIM + c0 * 4;
    const float* Bg1 = Wg + (size_t)m1 * H_DIM + c0 * 4;
    const float* Bu0 = Bg0 + (size_t)F_DIM * H_DIM;
    const float* Bu1 = Bg1 + (size_t)F_DIM * H_DIM;

    int tm = tid >> 4;   // 0..15 : 4-row micro tile
    int tn = tid & 15;   // 0..15 : 4-col micro tile

    float acc_g[4][4] = {};
    float acc_u[4][4] = {};

    // prologue: fill buffer 0
    float4 va0 = *(const float4*)A0,  va1 = *(const float4*)A1;
    float4 vg0 = *(const float4*)Bg0, vg1 = *(const float4*)Bg1;
    float4 vu0 = *(const float4*)Bu0, vu1 = *(const float4*)Bu1;
    store_t(sA[0],  va0, m0, c0); store_t(sA[0],  va1, m1, c0);
    store_t(sBg[0], vg0, m0, c0); store_t(sBg[0], vg1, m1, c0);
    store_t(sBu[0], vu0, m0, c0); store_t(sBu[0], vu1, m1, c0);
    __syncthreads();

    const int NK = H_DIM / BK;   // 32
    for (int kt = 0; kt < NK; kt++) {
        int buf = kt & 1;
        if (kt + 1 < NK) {
            int off = (kt + 1) * BK;
            va0 = *(const float4*)(A0 + off);  va1 = *(const float4*)(A1 + off);
            vg0 = *(const float4*)(Bg0 + off); vg1 = *(const float4*)(Bg1 + off);
            vu0 = *(const float4*)(Bu0 + off); vu1 = *(const float4*)(Bu1 + off);
        }
        const float* pA = sA[buf];
        const float* pG = sBg[buf];
        const float* pU = sBu[buf];
        #pragma unroll
        for (int k = 0; k < BK; k++) {
            int s = (k >> 2) & 7;
            float4 a  = *(const float4*)&pA[k * 64 + ((tm ^ s) << 2)];
            float4 bg = *(const float4*)&pG[k * 64 + ((tn ^ s) << 2)];
            float4 bu = *(const float4*)&pU[k * 64 + ((tn ^ s) << 2)];
            float av[4] = {a.x, a.y, a.z, a.w};
            float gv[4] = {bg.x, bg.y, bg.z, bg.w};
            float uv[4] = {bu.x, bu.y, bu.z, bu.w};
            #pragma unroll
            for (int i = 0; i < 4; i++)
                #pragma unroll
                for (int j = 0; j < 4; j++) {
                    acc_g[i][j] = fmaf(av[i], gv[j], acc_g[i][j]);
                    acc_u[i][j] = fmaf(av[i], uv[j], acc_u[i][j]);
                }
        }
        if (kt + 1 < NK) {
            int nb = buf ^ 1;
            store_t(sA[nb],  va0, m0, c0); store_t(sA[nb],  va1, m1, c0);
            store_t(sBg[nb], vg0, m0, c0); store_t(sBg[nb], vg1, m1, c0);
            store_t(sBu[nb], vu0, m0, c0); store_t(sBu[nb], vu1, m1, c0);
            __syncthreads();
        }
    }

    // epilogue: act = silu(gate) * up
    #pragma unroll
    for (int i = 0; i < 4; i++) {
        int m = tm * 4 + i;
        if (m < rows) {
            float* actp = g_act + (size_t)(row0 + m) * F_DIM + bx * BN + tn * 4;
            float4 o;
            o.x = (acc_g[i][0] / (1.f + expf(-acc_g[i][0]))) * acc_u[i][0];
            o.y = (acc_g[i][1] / (1.f + expf(-acc_g[i][1]))) * acc_u[i][1];
            o.z = (acc_g[i][2] / (1.f + expf(-acc_g[i][2]))) * acc_u[i][2];
            o.w = (acc_g[i][3] / (1.f + expf(-acc_g[i][3]))) * acc_u[i][3];
            *(float4*)actp = o;
        }
    }
}

// -------------------- GEMM2: out[t] += coef * (act @ Wd^T) --------------------
// grid.x = H/BN (16), grid.y = MAX_TILES
__global__ void __launch_bounds__(256, 2)
k_gemm2(const float* __restrict__ w_d, float* __restrict__ out) {
    int tile = blockIdx.y;
    if (tile >= g_num_tiles) return;
    int e = g_tile_e[tile], row0 = g_tile_row[tile], rows = g_tile_rows[tile];
    int bx = blockIdx.x;

    __shared__ float sA[2][BK * BM];
    __shared__ float sB[2][BK * BN];

    int tid = threadIdx.x;
    int r0 = tid >> 3, c0 = tid & 7;
    int m0 = r0, m1 = r0 + 32;

    const float* A0 = g_act + (size_t)(row0 + (m0 < rows ? m0 : 0)) * F_DIM + c0 * 4;
    const float* A1 = g_act + (size_t)(row0 + (m1 < rows ? m1 : 0)) * F_DIM + c0 * 4;
    const float* W  = w_d + (size_t)e * H_DIM * F_DIM + (size_t)(bx * BN) * F_DIM;
    const float* B0 = W + (size_t)m0 * F_DIM + c0 * 4;
    const float* B1 = W + (size_t)m1 * F_DIM + c0 * 4;

    int tm = tid >> 4, tn = tid & 15;
    float acc[4][4] = {};

    float4 va0 = *(const float4*)A0, va1 = *(const float4*)A1;
    float4 vb0 = *(const float4*)B0, vb1 = *(const float4*)B1;
    store_t(sA[0], va0, m0, c0); store_t(sA[0], va1, m1, c0);
    store_t(sB[0], vb0, m0, c0); store_t(sB[0], vb1, m1, c0);
    __syncthreads();

    const int NK = F_DIM / BK;   // 16
    for (int kt = 0; kt < NK; kt++) {
        int buf = kt & 1;
        if (kt + 1 < NK) {
            int off = (kt + 1) * BK;
            va0 = *(const float4*)(A0 + off); va1 = *(const float4*)(A1 + off);
            vb0 = *(const float4*)(B0 + off); vb1 = *(const float4*)(B1 + off);
        }
        const float* pA = sA[buf];
        const float* pB = sB[buf];
        #pragma unroll
        for (int k = 0; k < BK; k++) {
            int s = (k >> 2) & 7;
            float4 a = *(const float4*)&pA[k * 64 + ((tm ^ s) << 2)];
            float4 b = *(const float4*)&pB[k * 64 + ((tn ^ s) << 2)];
            float av[4] = {a.x, a.y, a.z, a.w};
            float bv[4] = {b.x, b.y, b.z, b.w};
            #pragma unroll
            for (int i = 0; i < 4; i++)
                #pragma unroll
                for (int j = 0; j < 4; j++)
                    acc[i][j] = fmaf(av[i], bv[j], acc[i][j]);
        }
        if (kt + 1 < NK) {
            int nb = buf ^ 1;
            store_t(sA[nb], va0, m0, c0); store_t(sA[nb], va1, m1, c0);
            store_t(sB[nb], vb0, m0, c0); store_t(sB[nb], vb1, m1, c0);
            __syncthreads();
        }
    }

    #pragma unroll
    for (int i = 0; i < 4; i++) {
        int m = tm * 4 + i;
        if (m < rows) {
            int   tok  = g_pair_token[row0 + m];
            float coef = g_pair_w[row0 + m];
            float* op = out + (size_t)tok * H_DIM + bx * BN + tn * 4;
            atomicAdd(&op[0], coef * acc[i][0]);
            atomicAdd(&op[1], coef * acc[i][1]);
            atomicAdd(&op[2], coef * acc[i][2]);
            atomicAdd(&op[3], coef * acc[i][3]);
        }
    }
}

// -------------------- launch --------------------
extern "C" void kernel_launch(void* const* d_in, const int* in_sizes, int n_in,
                              void* d_out, int out_size) {
    const float* hidden   = (const float*)d_in[0];
    const float* topk_w   = (const float*)d_in[1];
    const int*   topk_ids = (const int*)d_in[2];
    const float* w_gu     = (const float*)d_in[3];
    const float* w_d      = (const float*)d_in[4];
    float* out = (float*)d_out;

    cudaMemsetAsync(out, 0, (size_t)T_TOK * H_DIM * sizeof(float));

    k_init<<<1, 64>>>();
    k_count<<<TK / 256, 256>>>(topk_ids);
    k_scan<<<1, 1>>>();
    k_scatter<<<TK / 256, 256>>>(topk_ids, topk_w);

    dim3 g1(F_DIM / BN, MAX_TILES);
    k_gemm1<<<g1, 256>>>(hidden, w_gu);

    dim3 g2(H_DIM / BN, MAX_TILES);
    k_gemm2<<<g2, 256>>>(w_d, out);
}

// round 4
// speedup vs baseline: 1.1655x; 1.1655x over previous
#include <cuda_runtime.h>
#include <mma.h>
#include <cstdint>
#include <math.h>

using namespace nvcuda;

#define T_TOK 16384
#define H_DIM 1024
#define F_DIM 512
#define E_NUM 64
#define TK    (T_TOK * 2)            // 32768 routed pairs
#define BM    128                    // rows per m-tile
#define MAX_TILES (TK / BM + E_NUM)  // 320
#define BK    32
#define LDA   40                     // smem pitch (floats)

// -------------------- static device scratch --------------------
__device__ int   g_count[E_NUM];
__device__ int   g_offset[E_NUM];
__device__ int   g_cursor[E_NUM];
__device__ int   g_pair_token[TK];
__device__ float g_pair_w[TK];
__device__ int   g_pos_of[TK];
__device__ int   g_num_tiles;
__device__ int   g_tile_e[MAX_TILES];
__device__ int   g_tile_row[MAX_TILES];
__device__ int   g_tile_rows[MAX_TILES];
__device__ float g_act[(size_t)TK * F_DIM];   // 64 MB
__device__ float g_y[(size_t)TK * H_DIM];     // 128 MB

// round-to-nearest tf32 (portable PTX, sm_80+)
__device__ __forceinline__ float t32(float x) {
    uint32_t u;
    asm("cvt.rna.tf32.f32 %0, %1;" : "=r"(u) : "f"(x));
    return __uint_as_float(u);
}
__device__ __forceinline__ float silu_mul(float g, float u) {
    return g / (1.f + __expf(-g)) * u;
}

// -------------------- routing --------------------
__global__ void k_init() {
    if (threadIdx.x < E_NUM) g_count[threadIdx.x] = 0;
}
__global__ void k_count(const int* __restrict__ ids) {
    int i = blockIdx.x * blockDim.x + threadIdx.x;
    if (i < TK) atomicAdd(&g_count[ids[i]], 1);
}
__global__ void k_scan() {
    if (threadIdx.x == 0) {
        int off = 0, nt = 0;
        for (int e = 0; e < E_NUM; e++) {
            g_offset[e] = off; g_cursor[e] = 0;
            int c = g_count[e];
            for (int r = 0; r < c; r += BM) {
                g_tile_e[nt] = e;
                g_tile_row[nt] = off + r;
                g_tile_rows[nt] = (c - r < BM) ? (c - r) : BM;
                nt++;
            }
            off += c;
        }
        g_num_tiles = nt;
    }
}
__global__ void k_scatter(const int* __restrict__ ids, const float* __restrict__ w) {
    int i = blockIdx.x * blockDim.x + threadIdx.x;
    if (i < TK) {
        int e = ids[i];
        int pos = g_offset[e] + atomicAdd(&g_cursor[e], 1);
        g_pair_token[pos] = i >> 1;
        g_pair_w[pos] = w[i];
        g_pos_of[i] = pos;
    }
}

// -------------------- GEMM1: act = silu(X Wg^T) * (X Wu^T) --------------------
// grid(8, MAX_TILES), 512 thr. CTA tile: 128 rows x (64 gate + 64 up) cols, K=1024.
// Warps 4x4: warp tile 32 rows x 16 cols (per matrix).
__global__ void __launch_bounds__(512)
k_gemm1(const float* __restrict__ hidden, const float* __restrict__ w_gu) {
    int tile = blockIdx.y;
    if (tile >= g_num_tiles) return;
    const int e = g_tile_e[tile], row0 = g_tile_row[tile], rows = g_tile_rows[tile];
    const int bx = blockIdx.x;

    extern __shared__ float sm[];
    float* sA = sm;                   // [2][128*LDA]
    float* sG = sm + 2 * 128 * LDA;   // [2][64*LDA]
    float* sU = sG + 2 * 64 * LDA;    // [2][64*LDA]   total 20480 floats = 80KB

    __shared__ int s_tok[BM];

    const int tid  = threadIdx.x;
    const int warp = tid >> 5;
    const int wm = warp >> 2, wn = warp & 3;

    if (tid < BM) s_tok[tid] = g_pair_token[row0 + ((tid < rows) ? tid : 0)];
    __syncthreads();

    const float* Wg = w_gu + (size_t)e * (2 * F_DIM) * H_DIM + (size_t)(bx * 64) * H_DIM;
    const float* Wu = Wg + (size_t)F_DIM * H_DIM;

    // load mapping: chunk q -> row q>>3, float4 col (q&7)*4
    const int ra0 = tid >> 3, ca = (tid & 7) * 4;
    const int ra1 = ra0 + 64;
    const int rb  = tid >> 3;          // 0..63 for G/U

    float4 pa0, pa1, pg, pu;
    const float* A0p = hidden + (size_t)s_tok[ra0] * H_DIM + ca;
    const float* A1p = hidden + (size_t)s_tok[ra1] * H_DIM + ca;
    const float* Gp  = Wg + (size_t)rb * H_DIM + ca;
    const float* Up  = Wu + (size_t)rb * H_DIM + ca;

    wmma::fragment<wmma::accumulator, 16, 16, 8, float> ag[2], au[2];
    wmma::fill_fragment(ag[0], 0.f); wmma::fill_fragment(ag[1], 0.f);
    wmma::fill_fragment(au[0], 0.f); wmma::fill_fragment(au[1], 0.f);

    // prologue
    pa0 = *(const float4*)A0p; pa1 = *(const float4*)A1p;
    pg  = *(const float4*)Gp;  pu  = *(const float4*)Up;
    {
        float* a = sA; float* g = sG; float* u = sU;
        a[ra0*LDA+ca+0]=t32(pa0.x); a[ra0*LDA+ca+1]=t32(pa0.y); a[ra0*LDA+ca+2]=t32(pa0.z); a[ra0*LDA+ca+3]=t32(pa0.w);
        a[ra1*LDA+ca+0]=t32(pa1.x); a[ra1*LDA+ca+1]=t32(pa1.y); a[ra1*LDA+ca+2]=t32(pa1.z); a[ra1*LDA+ca+3]=t32(pa1.w);
        g[rb*LDA+ca+0]=t32(pg.x);  g[rb*LDA+ca+1]=t32(pg.y);  g[rb*LDA+ca+2]=t32(pg.z);  g[rb*LDA+ca+3]=t32(pg.w);
        u[rb*LDA+ca+0]=t32(pu.x);  u[rb*LDA+ca+1]=t32(pu.y);  u[rb*LDA+ca+2]=t32(pu.z);  u[rb*LDA+ca+3]=t32(pu.w);
    }
    __syncthreads();

    const int NCH = H_DIM / BK;   // 32
    for (int kt = 0; kt < NCH; kt++) {
        int buf = kt & 1;
        if (kt + 1 < NCH) {
            int k0 = (kt + 1) * BK;
            pa0 = *(const float4*)(A0p + k0); pa1 = *(const float4*)(A1p + k0);
            pg  = *(const float4*)(Gp + k0);  pu  = *(const float4*)(Up + k0);
        }
        const float* a = sA + buf * 128 * LDA;
        const float* g = sG + buf * 64 * LDA;
        const float* u = sU + buf * 64 * LDA;
        #pragma unroll
        for (int k8 = 0; k8 < BK / 8; k8++) {
            wmma::fragment<wmma::matrix_a, 16, 16, 8, wmma::precision::tf32, wmma::row_major> fa0, fa1;
            wmma::fragment<wmma::matrix_b, 16, 16, 8, wmma::precision::tf32, wmma::col_major> fg, fu;
            wmma::load_matrix_sync(fa0, a + (wm * 32) * LDA + k8 * 8, LDA);
            wmma::load_matrix_sync(fa1, a + (wm * 32 + 16) * LDA + k8 * 8, LDA);
            wmma::load_matrix_sync(fg,  g + (wn * 16) * LDA + k8 * 8, LDA);
            wmma::load_matrix_sync(fu,  u + (wn * 16) * LDA + k8 * 8, LDA);
            wmma::mma_sync(ag[0], fa0, fg, ag[0]);
            wmma::mma_sync(ag[1], fa1, fg, ag[1]);
            wmma::mma_sync(au[0], fa0, fu, au[0]);
            wmma::mma_sync(au[1], fa1, fu, au[1]);
        }
        if (kt + 1 < NCH) {
            int nb = buf ^ 1;
            float* a2 = sA + nb * 128 * LDA;
            float* g2 = sG + nb * 64 * LDA;
            float* u2 = sU + nb * 64 * LDA;
            a2[ra0*LDA+ca+0]=t32(pa0.x); a2[ra0*LDA+ca+1]=t32(pa0.y); a2[ra0*LDA+ca+2]=t32(pa0.z); a2[ra0*LDA+ca+3]=t32(pa0.w);
            a2[ra1*LDA+ca+0]=t32(pa1.x); a2[ra1*LDA+ca+1]=t32(pa1.y); a2[ra1*LDA+ca+2]=t32(pa1.z); a2[ra1*LDA+ca+3]=t32(pa1.w);
            g2[rb*LDA+ca+0]=t32(pg.x);  g2[rb*LDA+ca+1]=t32(pg.y);  g2[rb*LDA+ca+2]=t32(pg.z);  g2[rb*LDA+ca+3]=t32(pg.w);
            u2[rb*LDA+ca+0]=t32(pu.x);  u2[rb*LDA+ca+1]=t32(pu.y);  u2[rb*LDA+ca+2]=t32(pu.z);  u2[rb*LDA+ca+3]=t32(pu.w);
            __syncthreads();
        }
    }

    // -------- epilogue: stage accumulators, apply silu*up, write g_act --------
    __syncthreads();                       // done reading mainloop smem
    float* stg = sm;                       // gate stage [128][72]
    float* stu = sm + 128 * 72;            // up stage   [128][72]
    #pragma unroll
    for (int i = 0; i < 2; i++) {
        wmma::store_matrix_sync(stg + (wm * 32 + i * 16) * 72 + wn * 16, ag[i], 72, wmma::mem_row_major);
        wmma::store_matrix_sync(stu + (wm * 32 + i * 16) * 72 + wn * 16, au[i], 72, wmma::mem_row_major);
    }
    __syncthreads();
    #pragma unroll
    for (int i = 0; i < 4; i++) {          // 128 rows x 16 float4 = 2048 chunks
        int q = tid + i * 512;
        int r = q >> 4, c = (q & 15) * 4;
        if (r < rows) {
            float4 o;
            o.x = silu_mul(stg[r*72+c+0], stu[r*72+c+0]);
            o.y = silu_mul(stg[r*72+c+1], stu[r*72+c+1]);
            o.z = silu_mul(stg[r*72+c+2], stu[r*72+c+2]);
            o.w = silu_mul(stg[r*72+c+3], stu[r*72+c+3]);
            *(float4*)(g_act + (size_t)(row0 + r) * F_DIM + bx * 64 + c) = o;
        }
    }
}

// -------------------- GEMM2: y = coef * (act Wd^T) --------------------
// grid(8, MAX_TILES), 512 thr. CTA tile 128 rows x 128 cols, K=512.
// Warps 4x4: warp tile 32x32.
__global__ void __launch_bounds__(512)
k_gemm2(const float* __restrict__ w_d) {
    int tile = blockIdx.y;
    if (tile >= g_num_tiles) return;
    const int e = g_tile_e[tile], row0 = g_tile_row[tile], rows = g_tile_rows[tile];
    const int bx = blockIdx.x;

    extern __shared__ float sm[];
    float* sA = sm;                   // [2][128*LDA]
    float* sB = sm + 2 * 128 * LDA;   // [2][128*LDA]  total 20480 floats = 80KB

    __shared__ float s_w[BM];

    const int tid  = threadIdx.x;
    const int warp = tid >> 5;
    const int wm = warp >> 2, wn = warp & 3;

    if (tid < BM) s_w[tid] = g_pair_w[row0 + ((tid < rows) ? tid : 0)];
    __syncthreads();

    const float* W = w_d + (size_t)e * H_DIM * F_DIM + (size_t)(bx * 128) * F_DIM;

    const int r0q = tid >> 3, ca = (tid & 7) * 4;
    const int r1q = r0q + 64;
    const int ar0 = row0 + ((r0q < rows) ? r0q : 0);
    const int ar1 = row0 + ((r1q < rows) ? r1q : 0);

    const float* A0p = g_act + (size_t)ar0 * F_DIM + ca;
    const float* A1p = g_act + (size_t)ar1 * F_DIM + ca;
    const float* B0p = W + (size_t)r0q * F_DIM + ca;
    const float* B1p = W + (size_t)r1q * F_DIM + ca;

    wmma::fragment<wmma::accumulator, 16, 16, 8, float> acc[2][2];
    #pragma unroll
    for (int i = 0; i < 2; i++)
        #pragma unroll
        for (int j = 0; j < 2; j++) wmma::fill_fragment(acc[i][j], 0.f);

    float4 pa0, pa1, pb0, pb1;
    pa0 = *(const float4*)A0p; pa1 = *(const float4*)A1p;
    pb0 = *(const float4*)B0p; pb1 = *(const float4*)B1p;
    {
        float* a = sA; float* b = sB;
        a[r0q*LDA+ca+0]=t32(pa0.x); a[r0q*LDA+ca+1]=t32(pa0.y); a[r0q*LDA+ca+2]=t32(pa0.z); a[r0q*LDA+ca+3]=t32(pa0.w);
        a[r1q*LDA+ca+0]=t32(pa1.x); a[r1q*LDA+ca+1]=t32(pa1.y); a[r1q*LDA+ca+2]=t32(pa1.z); a[r1q*LDA+ca+3]=t32(pa1.w);
        b[r0q*LDA+ca+0]=t32(pb0.x); b[r0q*LDA+ca+1]=t32(pb0.y); b[r0q*LDA+ca+2]=t32(pb0.z); b[r0q*LDA+ca+3]=t32(pb0.w);
        b[r1q*LDA+ca+0]=t32(pb1.x); b[r1q*LDA+ca+1]=t32(pb1.y); b[r1q*LDA+ca+2]=t32(pb1.z); b[r1q*LDA+ca+3]=t32(pb1.w);
    }
    __syncthreads();

    const int NCH = F_DIM / BK;   // 16
    for (int kt = 0; kt < NCH; kt++) {
        int buf = kt & 1;
        if (kt + 1 < NCH) {
            int k0 = (kt + 1) * BK;
            pa0 = *(const float4*)(A0p + k0); pa1 = *(const float4*)(A1p + k0);
            pb0 = *(const float4*)(B0p + k0); pb1 = *(const float4*)(B1p + k0);
        }
        const float* a = sA + buf * 128 * LDA;
        const float* b = sB + buf * 128 * LDA;
        #pragma unroll
        for (int k8 = 0; k8 < BK / 8; k8++) {
            wmma::fragment<wmma::matrix_a, 16, 16, 8, wmma::precision::tf32, wmma::row_major> fa0, fa1;
            wmma::fragment<wmma::matrix_b, 16, 16, 8, wmma::precision::tf32, wmma::col_major> fb0, fb1;
            wmma::load_matrix_sync(fa0, a + (wm * 32) * LDA + k8 * 8, LDA);
            wmma::load_matrix_sync(fa1, a + (wm * 32 + 16) * LDA + k8 * 8, LDA);
            wmma::load_matrix_sync(fb0, b + (wn * 32) * LDA + k8 * 8, LDA);
            wmma::load_matrix_sync(fb1, b + (wn * 32 + 16) * LDA + k8 * 8, LDA);
            wmma::mma_sync(acc[0][0], fa0, fb0, acc[0][0]);
            wmma::mma_sync(acc[0][1], fa0, fb1, acc[0][1]);
            wmma::mma_sync(acc[1][0], fa1, fb0, acc[1][0]);
            wmma::mma_sync(acc[1][1], fa1, fb1, acc[1][1]);
        }
        if (kt + 1 < NCH) {
            int nb = buf ^ 1;
            float* a2 = sA + nb * 128 * LDA;
            float* b2 = sB + nb * 128 * LDA;
            a2[r0q*LDA+ca+0]=t32(pa0.x); a2[r0q*LDA+ca+1]=t32(pa0.y); a2[r0q*LDA+ca+2]=t32(pa0.z); a2[r0q*LDA+ca+3]=t32(pa0.w);
            a2[r1q*LDA+ca+0]=t32(pa1.x); a2[r1q*LDA+ca+1]=t32(pa1.y); a2[r1q*LDA+ca+2]=t32(pa1.z); a2[r1q*LDA+ca+3]=t32(pa1.w);
            b2[r0q*LDA+ca+0]=t32(pb0.x); b2[r0q*LDA+ca+1]=t32(pb0.y); b2[r0q*LDA+ca+2]=t32(pb0.z); b2[r0q*LDA+ca+3]=t32(pb0.w);
            b2[r1q*LDA+ca+0]=t32(pb1.x); b2[r1q*LDA+ca+1]=t32(pb1.y); b2[r1q*LDA+ca+2]=t32(pb1.z); b2[r1q*LDA+ca+3]=t32(pb1.w);
            __syncthreads();
        }
    }

    // -------- epilogue: stage, fold coef, write g_y --------
    __syncthreads();
    float* sty = sm;                       // [128][136]
    #pragma unroll
    for (int i = 0; i < 2; i++)
        #pragma unroll
        for (int j = 0; j < 2; j++)
            wmma::store_matrix_sync(sty + (wm * 32 + i * 16) * 136 + wn * 32 + j * 16,
                                    acc[i][j], 136, wmma::mem_row_major);
    __syncthreads();
    #pragma unroll
    for (int i = 0; i < 8; i++) {          // 128 rows x 32 float4 = 4096 chunks
        int q = tid + i * 512;
        int r = q >> 5, c = (q & 31) * 4;
        if (r < rows) {
            float coef = s_w[r];
            float4 o;
            o.x = coef * sty[r*136+c+0];
            o.y = coef * sty[r*136+c+1];
            o.z = coef * sty[r*136+c+2];
            o.w = coef * sty[r*136+c+3];
            *(float4*)(g_y + (size_t)(row0 + r) * H_DIM + bx * 128 + c) = o;
        }
    }
}

// -------------------- combine: out[t] = y[pos0] + y[pos1] --------------------
__global__ void k_combine(float* __restrict__ out) {
    int idx = blockIdx.x * 256 + threadIdx.x;   // over T*H/4 float4s
    int t = idx >> 8;                            // 256 float4 per token
    int c = idx & 255;
    int p0 = g_pos_of[2 * t], p1 = g_pos_of[2 * t + 1];
    const float4* y = (const float4*)g_y;
    float4 a = y[(size_t)p0 * (H_DIM / 4) + c];
    float4 b = y[(size_t)p1 * (H_DIM / 4) + c];
    ((float4*)out)[idx] = make_float4(a.x + b.x, a.y + b.y, a.z + b.z, a.w + b.w);
}

// -------------------- launch --------------------
#define SMEM_BYTES (20480 * 4)   // 80 KB for both GEMMs

extern "C" void kernel_launch(void* const* d_in, const int* in_sizes, int n_in,
                              void* d_out, int out_size) {
    const float* hidden   = (const float*)d_in[0];
    const float* topk_w   = (const float*)d_in[1];
    const int*   topk_ids = (const int*)d_in[2];
    const float* w_gu     = (const float*)d_in[3];
    const float* w_d      = (const float*)d_in[4];
    float* out = (float*)d_out;

    cudaFuncSetAttribute(k_gemm1, cudaFuncAttributeMaxDynamicSharedMemorySize, SMEM_BYTES);
    cudaFuncSetAttribute(k_gemm2, cudaFuncAttributeMaxDynamicSharedMemorySize, SMEM_BYTES);

    k_init<<<1, 64>>>();
    k_count<<<TK / 256, 256>>>(topk_ids);
    k_scan<<<1, 1>>>();
    k_scatter<<<TK / 256, 256>>>(topk_ids, topk_w);

    k_gemm1<<<dim3(F_DIM / 64, MAX_TILES), 512, SMEM_BYTES>>>(hidden, w_gu);
    k_gemm2<<<dim3(H_DIM / 128, MAX_TILES), 512, SMEM_BYTES>>>(w_d);
    k_combine<<<(T_TOK * H_DIM / 4) / 256, 256>>>(out);
}

// round 6
// speedup vs baseline: 1.4156x; 1.2146x over previous
#include <cuda_runtime.h>
#include <mma.h>
#include <cstdint>
#include <math.h>

using namespace nvcuda;

#define T_TOK 16384
#define H_DIM 1024
#define F_DIM 512
#define E_NUM 64
#define TK    (T_TOK * 2)            // 32768 routed pairs
#define BM    128                    // rows per m-tile
#define MAX_TILES (TK / BM + E_NUM)  // 320
#define BK    16
#define PCH   20                     // smem pitch (floats): conflict-free fragment loads

// -------------------- static device scratch --------------------
__device__ int   g_count[E_NUM];
__device__ int   g_offset[E_NUM];
__device__ int   g_cursor[E_NUM];
__device__ int   g_pair_token[TK];
__device__ float g_pair_w[TK];
__device__ int   g_pos_of[TK];
__device__ int   g_num_tiles;
__device__ int   g_tile_e[MAX_TILES];
__device__ int   g_tile_row[MAX_TILES];
__device__ int   g_tile_rows[MAX_TILES];
__device__ float g_act[(size_t)TK * F_DIM];   // 64 MB
__device__ float g_y[(size_t)TK * H_DIM];     // 128 MB

// round-to-nearest tf32
__device__ __forceinline__ float t32(float x) {
    uint32_t u;
    asm("cvt.rna.tf32.f32 %0, %1;" : "=r"(u) : "f"(x));
    return __uint_as_float(u);
}
__device__ __forceinline__ float silu_mul(float g, float u) {
    return g / (1.f + __expf(-g)) * u;
}
__device__ __forceinline__ void st4(float* p, float4 v) {
    p[0] = t32(v.x); p[1] = t32(v.y); p[2] = t32(v.z); p[3] = t32(v.w);
}

// -------------------- routing --------------------
__global__ void k_init() {
    if (threadIdx.x < E_NUM) g_count[threadIdx.x] = 0;
}
__global__ void k_count(const int* __restrict__ ids) {
    int i = blockIdx.x * blockDim.x + threadIdx.x;
    if (i < TK) atomicAdd(&g_count[ids[i]], 1);
}
__global__ void k_scan() {
    if (threadIdx.x == 0) {
        int off = 0, nt = 0;
        for (int e = 0; e < E_NUM; e++) {
            g_offset[e] = off; g_cursor[e] = 0;
            int c = g_count[e];
            for (int r = 0; r < c; r += BM) {
                g_tile_e[nt] = e;
                g_tile_row[nt] = off + r;
                g_tile_rows[nt] = (c - r < BM) ? (c - r) : BM;
                nt++;
            }
            off += c;
        }
        g_num_tiles = nt;
    }
}
__global__ void k_scatter(const int* __restrict__ ids, const float* __restrict__ w) {
    int i = blockIdx.x * blockDim.x + threadIdx.x;
    if (i < TK) {
        int e = ids[i];
        int pos = g_offset[e] + atomicAdd(&g_cursor[e], 1);
        g_pair_token[pos] = i >> 1;
        g_pair_w[pos] = w[i];
        g_pos_of[i] = pos;
    }
}

// ==================== GEMM1: act = silu(X Wg^T) * (X Wu^T) ====================
// grid(4, MAX_TILES), 512 thr (16 warps, 2x8). CTA tile 128 rows x 256 cols
// (128 gate || 128 up). Warp tile 64x32. K=1024, BK=16.
__global__ void __launch_bounds__(512)
k_gemm1(const float* __restrict__ hidden, const float* __restrict__ w_gu) {
    int tile = blockIdx.y;
    if (tile >= g_num_tiles) return;
    const int e = g_tile_e[tile], row0 = g_tile_row[tile], rows = g_tile_rows[tile];
    const int bx = blockIdx.x;

    extern __shared__ float sm[];
    // mainloop: sA[2][128*PCH] @ 0 ; sW[2][256*PCH] @ 5120   (15360 floats)
    // epilogue per 64-col half: stg[128][68] @ 0 ; stu[128][68] @ 8704 (17408 floats)
    __shared__ int s_tok[BM];

    const int tid  = threadIdx.x;
    const int warp = tid >> 5;
    const int wm = warp >> 3, wn = warp & 7;

    if (tid < BM) s_tok[tid] = g_pair_token[row0 + ((tid < rows) ? tid : 0)];
    __syncthreads();

    const float* Wg = w_gu + (size_t)e * (2 * F_DIM) * H_DIM + (size_t)(bx * 128) * H_DIM;
    const float* Wu = Wg + (size_t)F_DIM * H_DIM;

    const int arow = tid >> 2, acb = (tid & 3) * 4;
    const float* Ap = hidden + (size_t)s_tok[arow] * H_DIM + acb;
    const int wrow0 = tid >> 2;
    const int wrow1 = (tid + 512) >> 2;
    const float* Wp0 = (wrow0 < 128 ? Wg + (size_t)wrow0 * H_DIM
                                    : Wu + (size_t)(wrow0 - 128) * H_DIM) + acb;
    const float* Wp1 = (wrow1 < 128 ? Wg + (size_t)wrow1 * H_DIM
                                    : Wu + (size_t)(wrow1 - 128) * H_DIM) + acb;
    const int sa_off  = arow * PCH + acb;
    const int sw_off0 = wrow0 * PCH + acb;
    const int sw_off1 = wrow1 * PCH + acb;

    wmma::fragment<wmma::accumulator, 16, 16, 8, float> acc[4][2];
    #pragma unroll
    for (int i = 0; i < 4; i++)
        #pragma unroll
        for (int j = 0; j < 2; j++) wmma::fill_fragment(acc[i][j], 0.f);

    const int n0 = (wn < 4) ? wn * 32 : 128 + (wn - 4) * 32;

    {
        float4 va = *(const float4*)Ap;
        float4 v0 = *(const float4*)Wp0;
        float4 v1 = *(const float4*)Wp1;
        st4(sm + sa_off, va);
        st4(sm + 5120 + sw_off0, v0);
        st4(sm + 5120 + sw_off1, v1);
    }
    __syncthreads();

    const int NK = H_DIM / BK;   // 64
    for (int kt = 0; kt < NK; kt++) {
        const int buf = kt & 1;
        float4 va, v0, v1;
        if (kt + 1 < NK) {
            int k0 = (kt + 1) * BK;
            va = *(const float4*)(Ap + k0);
            v0 = *(const float4*)(Wp0 + k0);
            v1 = *(const float4*)(Wp1 + k0);
        }
        const float* a = sm + buf * 2560;
        const float* w = sm + 5120 + buf * 5120;
        #pragma unroll
        for (int k8 = 0; k8 < 2; k8++) {
            wmma::fragment<wmma::matrix_a, 16, 16, 8, wmma::precision::tf32, wmma::row_major> fa[4];
            wmma::fragment<wmma::matrix_b, 16, 16, 8, wmma::precision::tf32, wmma::col_major> fb[2];
            #pragma unroll
            for (int i = 0; i < 4; i++)
                wmma::load_matrix_sync(fa[i], a + (wm * 64 + i * 16) * PCH + k8 * 8, PCH);
            #pragma unroll
            for (int j = 0; j < 2; j++)
                wmma::load_matrix_sync(fb[j], w + (n0 + j * 16) * PCH + k8 * 8, PCH);
            #pragma unroll
            for (int i = 0; i < 4; i++)
                #pragma unroll
                for (int j = 0; j < 2; j++)
                    wmma::mma_sync(acc[i][j], fa[i], fb[j], acc[i][j]);
        }
        if (kt + 1 < NK) {
            int nb = buf ^ 1;
            st4(sm + nb * 2560 + sa_off, va);
            st4(sm + 5120 + nb * 5120 + sw_off0, v0);
            st4(sm + 5120 + nb * 5120 + sw_off1, v1);
            __syncthreads();
        }
    }

    // -------- epilogue: two 64-column half-passes (bounds-safe staging) --------
    // half h covers per-matrix cols [h*64, h*64+64); warps with ((wn&3)>>1)==h store.
    float* stg = sm;            // [128][68]
    float* stu = sm + 8704;     // [128][68]
    #pragma unroll
    for (int h = 0; h < 2; h++) {
        __syncthreads();        // prior smem readers done
        if (((wn & 3) >> 1) == h) {
            float* dst = (wn < 4) ? stg : stu;
            const int nloc = ((wn & 3) - 2 * h) * 32;   // 0 or 32
            #pragma unroll
            for (int i = 0; i < 4; i++)
                #pragma unroll
                for (int j = 0; j < 2; j++)
                    wmma::store_matrix_sync(dst + (wm * 64 + i * 16) * 68 + nloc + j * 16,
                                            acc[i][j], 68, wmma::mem_row_major);
        }
        __syncthreads();
        #pragma unroll
        for (int i = 0; i < 4; i++) {      // 128 rows x 16 float4 = 2048 chunks
            int q = tid + i * 512;
            int r = q >> 4, c = (q & 15) * 4;
            if (r < rows) {
                float4 o;
                o.x = silu_mul(stg[r*68+c+0], stu[r*68+c+0]);
                o.y = silu_mul(stg[r*68+c+1], stu[r*68+c+1]);
                o.z = silu_mul(stg[r*68+c+2], stu[r*68+c+2]);
                o.w = silu_mul(stg[r*68+c+3], stu[r*68+c+3]);
                *(float4*)(g_act + (size_t)(row0 + r) * F_DIM + bx * 128 + h * 64 + c) = o;
            }
        }
    }
}

// ==================== GEMM2: y = coef * (act Wd^T) ====================
// grid(4, MAX_TILES), 512 thr. CTA tile 128 rows x 256 cols, K=512, BK=16.
__global__ void __launch_bounds__(512)
k_gemm2(const float* __restrict__ w_d) {
    int tile = blockIdx.y;
    if (tile >= g_num_tiles) return;
    const int e = g_tile_e[tile], row0 = g_tile_row[tile], rows = g_tile_rows[tile];
    const int bx = blockIdx.x;

    extern __shared__ float sm[];
    // mainloop: sA[2][128*PCH] @ 0 ; sB[2][256*PCH] @ 5120
    // epilogue (per 128-col half): sty[128][132] @ 0
    __shared__ float s_w[BM];

    const int tid  = threadIdx.x;
    const int warp = tid >> 5;
    const int wm = warp >> 3, wn = warp & 7;

    if (tid < BM) s_w[tid] = g_pair_w[row0 + ((tid < rows) ? tid : 0)];
    __syncthreads();

    const float* W = w_d + (size_t)e * H_DIM * F_DIM + (size_t)(bx * 256) * F_DIM;

    const int arow = tid >> 2, acb = (tid & 3) * 4;
    const int ar = (arow < rows) ? arow : 0;
    const float* Ap = g_act + (size_t)(row0 + ar) * F_DIM + acb;
    const int wrow0 = tid >> 2, wrow1 = (tid + 512) >> 2;
    const float* Wp0 = W + (size_t)wrow0 * F_DIM + acb;
    const float* Wp1 = W + (size_t)wrow1 * F_DIM + acb;
    const int sa_off  = arow * PCH + acb;
    const int sw_off0 = wrow0 * PCH + acb;
    const int sw_off1 = wrow1 * PCH + acb;

    wmma::fragment<wmma::accumulator, 16, 16, 8, float> acc[4][2];
    #pragma unroll
    for (int i = 0; i < 4; i++)
        #pragma unroll
        for (int j = 0; j < 2; j++) wmma::fill_fragment(acc[i][j], 0.f);

    const int n0 = wn * 32;

    {
        float4 va = *(const float4*)Ap;
        float4 v0 = *(const float4*)Wp0;
        float4 v1 = *(const float4*)Wp1;
        st4(sm + sa_off, va);
        st4(sm + 5120 + sw_off0, v0);
        st4(sm + 5120 + sw_off1, v1);
    }
    __syncthreads();

    const int NK = F_DIM / BK;   // 32
    for (int kt = 0; kt < NK; kt++) {
        const int buf = kt & 1;
        float4 va, v0, v1;
        if (kt + 1 < NK) {
            int k0 = (kt + 1) * BK;
            va = *(const float4*)(Ap + k0);
            v0 = *(const float4*)(Wp0 + k0);
            v1 = *(const float4*)(Wp1 + k0);
        }
        const float* a = sm + buf * 2560;
        const float* b = sm + 5120 + buf * 5120;
        #pragma unroll
        for (int k8 = 0; k8 < 2; k8++) {
            wmma::fragment<wmma::matrix_a, 16, 16, 8, wmma::precision::tf32, wmma::row_major> fa[4];
            wmma::fragment<wmma::matrix_b, 16, 16, 8, wmma::precision::tf32, wmma::col_major> fb[2];
            #pragma unroll
            for (int i = 0; i < 4; i++)
                wmma::load_matrix_sync(fa[i], a + (wm * 64 + i * 16) * PCH + k8 * 8, PCH);
            #pragma unroll
            for (int j = 0; j < 2; j++)
                wmma::load_matrix_sync(fb[j], b + (n0 + j * 16) * PCH + k8 * 8, PCH);
            #pragma unroll
            for (int i = 0; i < 4; i++)
                #pragma unroll
                for (int j = 0; j < 2; j++)
                    wmma::mma_sync(acc[i][j], fa[i], fb[j], acc[i][j]);
        }
        if (kt + 1 < NK) {
            int nb = buf ^ 1;
            st4(sm + nb * 2560 + sa_off, va);
            st4(sm + 5120 + nb * 5120 + sw_off0, v0);
            st4(sm + 5120 + nb * 5120 + sw_off1, v1);
            __syncthreads();
        }
    }

    // -------- epilogue in two 128-col halves --------
    float* sty = sm;   // [128][132]
    #pragma unroll
    for (int h = 0; h < 2; h++) {
        __syncthreads();
        if ((wn >> 2) == h) {
            #pragma unroll
            for (int i = 0; i < 4; i++)
                #pragma unroll
                for (int j = 0; j < 2; j++)
                    wmma::store_matrix_sync(sty + (wm * 64 + i * 16) * 132 + (wn & 3) * 32 + j * 16,
                                            acc[i][j], 132, wmma::mem_row_major);
        }
        __syncthreads();
        #pragma unroll
        for (int i = 0; i < 8; i++) {      // 128 rows x 32 float4
            int q = tid + i * 512;
            int r = q >> 5, c = (q & 31) * 4;
            if (r < rows) {
                float coef = s_w[r];
                float4 o;
                o.x = coef * sty[r*132+c+0];
                o.y = coef * sty[r*132+c+1];
                o.z = coef * sty[r*132+c+2];
                o.w = coef * sty[r*132+c+3];
                *(float4*)(g_y + (size_t)(row0 + r) * H_DIM + bx * 256 + h * 128 + c) = o;
            }
        }
    }
}

// -------------------- combine: out[t] = y[pos0] + y[pos1] --------------------
__global__ void k_combine(float* __restrict__ out) {
    int idx = blockIdx.x * 256 + threadIdx.x;
    int t = idx >> 8;
    int c = idx & 255;
    int p0 = g_pos_of[2 * t], p1 = g_pos_of[2 * t + 1];
    const float4* y = (const float4*)g_y;
    float4 a = y[(size_t)p0 * (H_DIM / 4) + c];
    float4 b = y[(size_t)p1 * (H_DIM / 4) + c];
    ((float4*)out)[idx] = make_float4(a.x + b.x, a.y + b.y, a.z + b.z, a.w + b.w);
}

// -------------------- launch --------------------
#define SMEM_G1 (17408 * 4)   // max(mainloop 15360, stage 17408) floats
#define SMEM_G2 (16896 * 4)   // max(mainloop 15360, stage 16896) floats

extern "C" void kernel_launch(void* const* d_in, const int* in_sizes, int n_in,
                              void* d_out, int out_size) {
    const float* hidden   = (const float*)d_in[0];
    const float* topk_w   = (const float*)d_in[1];
    const int*   topk_ids = (const int*)d_in[2];
    const float* w_gu     = (const float*)d_in[3];
    const float* w_d      = (const float*)d_in[4];
    float* out = (float*)d_out;

    cudaFuncSetAttribute(k_gemm1, cudaFuncAttributeMaxDynamicSharedMemorySize, SMEM_G1);
    cudaFuncSetAttribute(k_gemm2, cudaFuncAttributeMaxDynamicSharedMemorySize, SMEM_G2);

    k_init<<<1, 64>>>();
    k_count<<<TK / 256, 256>>>(topk_ids);
    k_scan<<<1, 1>>>();
    k_scatter<<<TK / 256, 256>>>(topk_ids, topk_w);

    k_gemm1<<<dim3(F_DIM / 128, MAX_TILES), 512, SMEM_G1>>>(hidden, w_gu);
    k_gemm2<<<dim3(H_DIM / 256, MAX_TILES), 512, SMEM_G2>>>(w_d);
    k_combine<<<(T_TOK * H_DIM / 4) / 256, 256>>>(out);
}

// round 7
// speedup vs baseline: 1.6622x; 1.1742x over previous
#include <cuda_runtime.h>
#include <cuda_bf16.h>
#include <mma.h>
#include <cstdint>
#include <math.h>

using namespace nvcuda;

#define T_TOK 16384
#define H_DIM 1024
#define F_DIM 512
#define E_NUM 64
#define TK    (T_TOK * 2)            // 32768 routed pairs
#define BM    128
#define MAX_TILES (TK / BM + E_NUM)  // 320
#define BK    16
#define PCH   24                     // bf16 smem pitch (elems): 48B rows -> conflict-free LDSM

// -------------------- static device scratch --------------------
__device__ int   g_count[E_NUM];
__device__ int   g_offset[E_NUM];
__device__ int   g_cursor[E_NUM];
__device__ int   g_pair_token[TK];
__device__ float g_pair_w[TK];
__device__ int   g_pos_of[TK];
__device__ int   g_num_tiles;
__device__ int   g_tile_e[MAX_TILES];
__device__ int   g_tile_row[MAX_TILES];
__device__ int   g_tile_rows[MAX_TILES];
__device__ float g_act[(size_t)TK * F_DIM];   // 64 MB
__device__ float g_y[(size_t)TK * H_DIM];     // 128 MB

__device__ __forceinline__ float silu_mul(float g, float u) {
    return g / (1.f + __expf(-g)) * u;
}

// split fp32x4 -> bf16 hi plane + bf16 lo (residual) plane
__device__ __forceinline__ void split_st(__nv_bfloat16* hi, __nv_bfloat16* lo, float4 v) {
    __nv_bfloat162 h01 = __floats2bfloat162_rn(v.x, v.y);
    __nv_bfloat162 h23 = __floats2bfloat162_rn(v.z, v.w);
    float2 f01 = __bfloat1622float2(h01);
    float2 f23 = __bfloat1622float2(h23);
    __nv_bfloat162 l01 = __floats2bfloat162_rn(v.x - f01.x, v.y - f01.y);
    __nv_bfloat162 l23 = __floats2bfloat162_rn(v.z - f23.x, v.w - f23.y);
    *(__nv_bfloat162*)(hi)     = h01;
    *(__nv_bfloat162*)(hi + 2) = h23;
    *(__nv_bfloat162*)(lo)     = l01;
    *(__nv_bfloat162*)(lo + 2) = l23;
}

typedef wmma::fragment<wmma::matrix_a, 16, 16, 16, __nv_bfloat16, wmma::row_major> FragA;
typedef wmma::fragment<wmma::matrix_b, 16, 16, 16, __nv_bfloat16, wmma::col_major> FragB;
typedef wmma::fragment<wmma::accumulator, 16, 16, 16, float> FragC;

// -------------------- routing (3 launches; gemm1 = my launch #4 for ncu) ----
__global__ void k_count(const int* __restrict__ ids) {
    __shared__ int cnt;
    if (threadIdx.x == 0) cnt = 0;
    __syncthreads();
    int local = 0;
    int e = blockIdx.x;
    for (int i = threadIdx.x; i < TK; i += 256) local += (ids[i] == e);
    #pragma unroll
    for (int o = 16; o > 0; o >>= 1) local += __shfl_down_sync(0xFFFFFFFF, local, o);
    if ((threadIdx.x & 31) == 0) atomicAdd(&cnt, local);
    __syncthreads();
    if (threadIdx.x == 0) g_count[e] = cnt;
}
__global__ void k_scan() {
    if (threadIdx.x == 0) {
        int off = 0, nt = 0;
        for (int e = 0; e < E_NUM; e++) {
            g_offset[e] = off; g_cursor[e] = 0;
            int c = g_count[e];
            for (int r = 0; r < c; r += BM) {
                g_tile_e[nt] = e;
                g_tile_row[nt] = off + r;
                g_tile_rows[nt] = (c - r < BM) ? (c - r) : BM;
                nt++;
            }
            off += c;
        }
        g_num_tiles = nt;
    }
}
__global__ void k_scatter(const int* __restrict__ ids, const float* __restrict__ w) {
    int i = blockIdx.x * blockDim.x + threadIdx.x;
    if (i < TK) {
        int e = ids[i];
        int pos = g_offset[e] + atomicAdd(&g_cursor[e], 1);
        g_pair_token[pos] = i >> 1;
        g_pair_w[pos] = w[i];
        g_pos_of[i] = pos;
    }
}

// smem bf16 layout (elems), shared by both GEMMs:
//   Ahi[buf] @ buf*3072, Alo[buf] @ 6144 + buf*3072          (A: 128 x PCH)
//   Whi[buf] @ 12288 + buf*6144, Wlo[buf] @ 24576 + buf*6144 (W: 256 x PCH)
// total 36864 bf16 = 73728 B
#define A_HI(buf) ((buf) * 3072)
#define A_LO(buf) (6144 + (buf) * 3072)
#define W_HI(buf) (12288 + (buf) * 6144)
#define W_LO(buf) (24576 + (buf) * 6144)

// ==================== GEMM1: act = silu(X Wg^T) * (X Wu^T) ====================
// grid(4, MAX_TILES), 512 thr (16 warps 2x8). CTA 128 x 256 (128 gate || 128 up),
// warp tile 64x32, K=1024, BK=16, split-bf16 (3 mma per tile-k16).
__global__ void __launch_bounds__(512)
k_gemm1(const float* __restrict__ hidden, const float* __restrict__ w_gu) {
    int tile = blockIdx.y;
    if (tile >= g_num_tiles) return;
    const int e = g_tile_e[tile], row0 = g_tile_row[tile], rows = g_tile_rows[tile];
    const int bx = blockIdx.x;

    extern __shared__ float sm[];
    __nv_bfloat16* bsm = (__nv_bfloat16*)sm;
    __shared__ int s_tok[BM];

    const int tid  = threadIdx.x;
    const int warp = tid >> 5;
    const int wm = warp >> 3, wn = warp & 7;

    if (tid < BM) s_tok[tid] = g_pair_token[row0 + ((tid < rows) ? tid : 0)];
    __syncthreads();

    const float* Wg = w_gu + (size_t)e * (2 * F_DIM) * H_DIM + (size_t)(bx * 128) * H_DIM;
    const float* Wu = Wg + (size_t)F_DIM * H_DIM;

    const int arow = tid >> 2, acb = (tid & 3) * 4;
    const float* Ap = hidden + (size_t)s_tok[arow] * H_DIM + acb;
    const int wrow0 = tid >> 2;
    const int wrow1 = (tid + 512) >> 2;
    const float* Wp0 = (wrow0 < 128 ? Wg + (size_t)wrow0 * H_DIM
                                    : Wu + (size_t)(wrow0 - 128) * H_DIM) + acb;
    const float* Wp1 = (wrow1 < 128 ? Wg + (size_t)wrow1 * H_DIM
                                    : Wu + (size_t)(wrow1 - 128) * H_DIM) + acb;
    const int sa_off  = arow * PCH + acb;
    const int sw_off0 = wrow0 * PCH + acb;
    const int sw_off1 = wrow1 * PCH + acb;

    FragC acc[4][2];
    #pragma unroll
    for (int i = 0; i < 4; i++)
        #pragma unroll
        for (int j = 0; j < 2; j++) wmma::fill_fragment(acc[i][j], 0.f);

    const int n0 = (wn < 4) ? wn * 32 : 128 + (wn - 4) * 32;

    {   // prologue -> buffer 0
        float4 va = *(const float4*)Ap;
        float4 v0 = *(const float4*)Wp0;
        float4 v1 = *(const float4*)Wp1;
        split_st(bsm + A_HI(0) + sa_off,  bsm + A_LO(0) + sa_off,  va);
        split_st(bsm + W_HI(0) + sw_off0, bsm + W_LO(0) + sw_off0, v0);
        split_st(bsm + W_HI(0) + sw_off1, bsm + W_LO(0) + sw_off1, v1);
    }
    __syncthreads();

    const int NK = H_DIM / BK;   // 64
    for (int kt = 0; kt < NK; kt++) {
        const int buf = kt & 1;
        float4 va, v0, v1;
        if (kt + 1 < NK) {
            int k0 = (kt + 1) * BK;
            va = *(const float4*)(Ap + k0);
            v0 = *(const float4*)(Wp0 + k0);
            v1 = *(const float4*)(Wp1 + k0);
        }
        const __nv_bfloat16* ah = bsm + A_HI(buf);
        const __nv_bfloat16* al = bsm + A_LO(buf);
        const __nv_bfloat16* wh = bsm + W_HI(buf);
        const __nv_bfloat16* wl = bsm + W_LO(buf);

        FragB fbh[2], fbl[2];
        #pragma unroll
        for (int j = 0; j < 2; j++) {
            wmma::load_matrix_sync(fbh[j], wh + (n0 + j * 16) * PCH, PCH);
            wmma::load_matrix_sync(fbl[j], wl + (n0 + j * 16) * PCH, PCH);
        }
        #pragma unroll
        for (int i = 0; i < 4; i++) {
            FragA fah, fal;
            wmma::load_matrix_sync(fah, ah + (wm * 64 + i * 16) * PCH, PCH);
            wmma::load_matrix_sync(fal, al + (wm * 64 + i * 16) * PCH, PCH);
            #pragma unroll
            for (int j = 0; j < 2; j++) {
                wmma::mma_sync(acc[i][j], fah, fbh[j], acc[i][j]);
                wmma::mma_sync(acc[i][j], fal, fbh[j], acc[i][j]);
                wmma::mma_sync(acc[i][j], fah, fbl[j], acc[i][j]);
            }
        }
        if (kt + 1 < NK) {
            int nb = buf ^ 1;
            split_st(bsm + A_HI(nb) + sa_off,  bsm + A_LO(nb) + sa_off,  va);
            split_st(bsm + W_HI(nb) + sw_off0, bsm + W_LO(nb) + sw_off0, v0);
            split_st(bsm + W_HI(nb) + sw_off1, bsm + W_LO(nb) + sw_off1, v1);
            __syncthreads();
        }
    }

    // -------- epilogue: two 64-column half-passes --------
    float* stg = sm;            // [128][68]
    float* stu = sm + 8704;     // [128][68]
    #pragma unroll
    for (int h = 0; h < 2; h++) {
        __syncthreads();
        if (((wn & 3) >> 1) == h) {
            float* dst = (wn < 4) ? stg : stu;
            const int nloc = ((wn & 3) - 2 * h) * 32;   // 0 or 32
            #pragma unroll
            for (int i = 0; i < 4; i++)
                #pragma unroll
                for (int j = 0; j < 2; j++)
                    wmma::store_matrix_sync(dst + (wm * 64 + i * 16) * 68 + nloc + j * 16,
                                            acc[i][j], 68, wmma::mem_row_major);
        }
        __syncthreads();
        #pragma unroll
        for (int i = 0; i < 4; i++) {      // 128 rows x 16 float4
            int q = tid + i * 512;
            int r = q >> 4, c = (q & 15) * 4;
            if (r < rows) {
                float4 o;
                o.x = silu_mul(stg[r*68+c+0], stu[r*68+c+0]);
                o.y = silu_mul(stg[r*68+c+1], stu[r*68+c+1]);
                o.z = silu_mul(stg[r*68+c+2], stu[r*68+c+2]);
                o.w = silu_mul(stg[r*68+c+3], stu[r*68+c+3]);
                *(float4*)(g_act + (size_t)(row0 + r) * F_DIM + bx * 128 + h * 64 + c) = o;
            }
        }
    }
}

// ==================== GEMM2: y = coef * (act Wd^T) ====================
// grid(4, MAX_TILES), 512 thr. CTA 128 x 256, K=512, BK=16, split-bf16.
__global__ void __launch_bounds__(512)
k_gemm2(const float* __restrict__ w_d) {
    int tile = blockIdx.y;
    if (tile >= g_num_tiles) return;
    const int e = g_tile_e[tile], row0 = g_tile_row[tile], rows = g_tile_rows[tile];
    const int bx = blockIdx.x;

    extern __shared__ float sm[];
    __nv_bfloat16* bsm = (__nv_bfloat16*)sm;
    __shared__ float s_w[BM];

    const int tid  = threadIdx.x;
    const int warp = tid >> 5;
    const int wm = warp >> 3, wn = warp & 7;

    if (tid < BM) s_w[tid] = g_pair_w[row0 + ((tid < rows) ? tid : 0)];
    __syncthreads();

    const float* W = w_d + (size_t)e * H_DIM * F_DIM + (size_t)(bx * 256) * F_DIM;

    const int arow = tid >> 2, acb = (tid & 3) * 4;
    const int ar = (arow < rows) ? arow : 0;
    const float* Ap = g_act + (size_t)(row0 + ar) * F_DIM + acb;
    const int wrow0 = tid >> 2, wrow1 = (tid + 512) >> 2;
    const float* Wp0 = W + (size_t)wrow0 * F_DIM + acb;
    const float* Wp1 = W + (size_t)wrow1 * F_DIM + acb;
    const int sa_off  = arow * PCH + acb;
    const int sw_off0 = wrow0 * PCH + acb;
    const int sw_off1 = wrow1 * PCH + acb;

    FragC acc[4][2];
    #pragma unroll
    for (int i = 0; i < 4; i++)
        #pragma unroll
        for (int j = 0; j < 2; j++) wmma::fill_fragment(acc[i][j], 0.f);

    const int n0 = wn * 32;

    {
        float4 va = *(const float4*)Ap;
        float4 v0 = *(const float4*)Wp0;
        float4 v1 = *(const float4*)Wp1;
        split_st(bsm + A_HI(0) + sa_off,  bsm + A_LO(0) + sa_off,  va);
        split_st(bsm + W_HI(0) + sw_off0, bsm + W_LO(0) + sw_off0, v0);
        split_st(bsm + W_HI(0) + sw_off1, bsm + W_LO(0) + sw_off1, v1);
    }
    __syncthreads();

    const int NK = F_DIM / BK;   // 32
    for (int kt = 0; kt < NK; kt++) {
        const int buf = kt & 1;
        float4 va, v0, v1;
        if (kt + 1 < NK) {
            int k0 = (kt + 1) * BK;
            va = *(const float4*)(Ap + k0);
            v0 = *(const float4*)(Wp0 + k0);
            v1 = *(const float4*)(Wp1 + k0);
        }
        const __nv_bfloat16* ah = bsm + A_HI(buf);
        const __nv_bfloat16* al = bsm + A_LO(buf);
        const __nv_bfloat16* wh = bsm + W_HI(buf);
        const __nv_bfloat16* wl = bsm + W_LO(buf);

        FragB fbh[2], fbl[2];
        #pragma unroll
        for (int j = 0; j < 2; j++) {
            wmma::load_matrix_sync(fbh[j], wh + (n0 + j * 16) * PCH, PCH);
            wmma::load_matrix_sync(fbl[j], wl + (n0 + j * 16) * PCH, PCH);
        }
        #pragma unroll
        for (int i = 0; i < 4; i++) {
            FragA fah, fal;
            wmma::load_matrix_sync(fah, ah + (wm * 64 + i * 16) * PCH, PCH);
            wmma::load_matrix_sync(fal, al + (wm * 64 + i * 16) * PCH, PCH);
            #pragma unroll
            for (int j = 0; j < 2; j++) {
                wmma::mma_sync(acc[i][j], fah, fbh[j], acc[i][j]);
                wmma::mma_sync(acc[i][j], fal, fbh[j], acc[i][j]);
                wmma::mma_sync(acc[i][j], fah, fbl[j], acc[i][j]);
            }
        }
        if (kt + 1 < NK) {
            int nb = buf ^ 1;
            split_st(bsm + A_HI(nb) + sa_off,  bsm + A_LO(nb) + sa_off,  va);
            split_st(bsm + W_HI(nb) + sw_off0, bsm + W_LO(nb) + sw_off0, v0);
            split_st(bsm + W_HI(nb) + sw_off1, bsm + W_LO(nb) + sw_off1, v1);
            __syncthreads();
        }
    }

    // -------- epilogue in two 128-col halves --------
    float* sty = sm;   // [128][132]
    #pragma unroll
    for (int h = 0; h < 2; h++) {
        __syncthreads();
        if ((wn >> 2) == h) {
            #pragma unroll
            for (int i = 0; i < 4; i++)
                #pragma unroll
                for (int j = 0; j < 2; j++)
                    wmma::store_matrix_sync(sty + (wm * 64 + i * 16) * 132 + (wn & 3) * 32 + j * 16,
                                            acc[i][j], 132, wmma::mem_row_major);
        }
        __syncthreads();
        #pragma unroll
        for (int i = 0; i < 8; i++) {      // 128 rows x 32 float4
            int q = tid + i * 512;
            int r = q >> 5, c = (q & 31) * 4;
            if (r < rows) {
                float coef = s_w[r];
                float4 o;
                o.x = coef * sty[r*132+c+0];
                o.y = coef * sty[r*132+c+1];
                o.z = coef * sty[r*132+c+2];
                o.w = coef * sty[r*132+c+3];
                *(float4*)(g_y + (size_t)(row0 + r) * H_DIM + bx * 256 + h * 128 + c) = o;
            }
        }
    }
}

// -------------------- combine: out[t] = y[pos0] + y[pos1] --------------------
__global__ void k_combine(float* __restrict__ out) {
    int idx = blockIdx.x * 256 + threadIdx.x;
    int t = idx >> 8;
    int c = idx & 255;
    int p0 = g_pos_of[2 * t], p1 = g_pos_of[2 * t + 1];
    const float4* y = (const float4*)g_y;
    float4 a = y[(size_t)p0 * (H_DIM / 4) + c];
    float4 b = y[(size_t)p1 * (H_DIM / 4) + c];
    ((float4*)out)[idx] = make_float4(a.x + b.x, a.y + b.y, a.z + b.z, a.w + b.w);
}

// -------------------- launch --------------------
#define SMEM_BYTES 73728   // mainloop bf16 region (> both epilogue stages)

extern "C" void kernel_launch(void* const* d_in, const int* in_sizes, int n_in,
                              void* d_out, int out_size) {
    const float* hidden   = (const float*)d_in[0];
    const float* topk_w   = (const float*)d_in[1];
    const int*   topk_ids = (const int*)d_in[2];
    const float* w_gu     = (const float*)d_in[3];
    const float* w_d      = (const float*)d_in[4];
    float* out = (float*)d_out;

    cudaFuncSetAttribute(k_gemm1, cudaFuncAttributeMaxDynamicSharedMemorySize, SMEM_BYTES);
    cudaFuncSetAttribute(k_gemm2, cudaFuncAttributeMaxDynamicSharedMemorySize, SMEM_BYTES);

    k_count<<<E_NUM, 256>>>(topk_ids);                    // launch 1
    k_scan<<<1, 1>>>();                                   // launch 2
    k_scatter<<<TK / 256, 256>>>(topk_ids, topk_w);       // launch 3
    k_gemm1<<<dim3(F_DIM / 128, MAX_TILES), 512, SMEM_BYTES>>>(hidden, w_gu);  // launch 4 (ncu slot)
    k_gemm2<<<dim3(H_DIM / 256, MAX_TILES), 512, SMEM_BYTES>>>(w_d);
    k_combine<<<(T_TOK * H_DIM / 4) / 256, 256>>>(out);
}

// round 9
// speedup vs baseline: 1.6884x; 1.0157x over previous
#include <cuda_runtime.h>
#include <cuda_bf16.h>
#include <mma.h>
#include <cstdint>
#include <math.h>

using namespace nvcuda;

#define T_TOK 16384
#define H_DIM 1024
#define F_DIM 512
#define E_NUM 64
#define TK    (T_TOK * 2)            // 32768 routed pairs
#define BM    128
#define MAX_TILES (TK / BM + E_NUM)  // 320
#define PCH   24                     // bf16 smem pitch: 48B rows -> conflict-free LDSM

// split conversion ranges (float4 units)
#define N4_HID (T_TOK * H_DIM / 4)
#define N4_WGU (E_NUM * 2 * F_DIM * H_DIM / 4)
#define N4_WD  (E_NUM * H_DIM * F_DIM / 4)
#define N4_ALL (N4_HID + N4_WGU + N4_WD)

// -------------------- static device scratch --------------------
__device__ int   g_offset[E_NUM];
__device__ int   g_cursor[E_NUM];
__device__ int   g_pair_token[TK];
__device__ float g_pair_w[TK];
__device__ int   g_pos_of[TK];
__device__ int   g_num_tiles;
__device__ int   g_tile_e[MAX_TILES];
__device__ int   g_tile_row[MAX_TILES];
__device__ int   g_tile_rows[MAX_TILES];

__device__ __nv_bfloat16 g_hid_hi[(size_t)T_TOK * H_DIM];
__device__ __nv_bfloat16 g_hid_lo[(size_t)T_TOK * H_DIM];
__device__ __nv_bfloat16 g_wgu_hi[(size_t)E_NUM * 2 * F_DIM * H_DIM];
__device__ __nv_bfloat16 g_wgu_lo[(size_t)E_NUM * 2 * F_DIM * H_DIM];
__device__ __nv_bfloat16 g_wd_hi[(size_t)E_NUM * H_DIM * F_DIM];
__device__ __nv_bfloat16 g_wd_lo[(size_t)E_NUM * H_DIM * F_DIM];
__device__ __nv_bfloat16 g_act_hi[(size_t)TK * F_DIM];
__device__ __nv_bfloat16 g_act_lo[(size_t)TK * F_DIM];
__device__ float g_y[(size_t)TK * H_DIM];

// -------------------- helpers --------------------
__device__ __forceinline__ float silu_mul(float g, float u) {
    return g / (1.f + __expf(-g)) * u;
}
__device__ __forceinline__ void split_store(__nv_bfloat16* hi, __nv_bfloat16* lo, float4 v) {
    __nv_bfloat162 h01 = __floats2bfloat162_rn(v.x, v.y);
    __nv_bfloat162 h23 = __floats2bfloat162_rn(v.z, v.w);
    float2 f01 = __bfloat1622float2(h01);
    float2 f23 = __bfloat1622float2(h23);
    __nv_bfloat162 l01 = __floats2bfloat162_rn(v.x - f01.x, v.y - f01.y);
    __nv_bfloat162 l23 = __floats2bfloat162_rn(v.z - f23.x, v.w - f23.y);
    *(__nv_bfloat162*)(hi)     = h01;
    *(__nv_bfloat162*)(hi + 2) = h23;
    *(__nv_bfloat162*)(lo)     = l01;
    *(__nv_bfloat162*)(lo + 2) = l23;
}

#define CP_ASYNC(dst, src) \
    asm volatile("cp.async.cg.shared.global [%0], [%1], 16;" :: "r"(dst), "l"(src))
#define CP_COMMIT() asm volatile("cp.async.commit_group;" ::: "memory")
#define CP_WAIT1()  asm volatile("cp.async.wait_group 1;" ::: "memory")

__device__ __forceinline__ uint32_t smem_u32(const void* p) {
    uint32_t a;
    asm("{ .reg .u64 t; cvta.to.shared.u64 t, %1; cvt.u32.u64 %0, t; }" : "=r"(a) : "l"(p));
    return a;
}

typedef wmma::fragment<wmma::matrix_a, 16, 16, 16, __nv_bfloat16, wmma::row_major> FragA;
typedef wmma::fragment<wmma::matrix_b, 16, 16, 16, __nv_bfloat16, wmma::col_major> FragB;
typedef wmma::fragment<wmma::accumulator, 16, 16, 16, float> FragC;

// smem stage layout (bf16 elems): A_hi @0, A_lo @3072, W_hi @6144, W_lo @9216
// stage = 12288 elems = 24576 B; 3 stages = 73728 B
#define STAGE_B 24576
#define SMEM_BYTES 73728

// -------------------- split conversion --------------------
__global__ void k_split_all(const float* __restrict__ hidden,
                            const float* __restrict__ wgu,
                            const float* __restrict__ wd) {
    size_t i = (size_t)blockIdx.x * 256 + threadIdx.x;
    const float4* src;
    __nv_bfloat16 *hi, *lo;
    size_t off;
    if (i < N4_HID)              { src = (const float4*)hidden; hi = g_hid_hi; lo = g_hid_lo; off = i; }
    else if (i < N4_HID + N4_WGU){ src = (const float4*)wgu;    hi = g_wgu_hi; lo = g_wgu_lo; off = i - N4_HID; }
    else                         { src = (const float4*)wd;     hi = g_wd_hi;  lo = g_wd_lo;  off = i - N4_HID - N4_WGU; }
    float4 v = src[off];
    split_store(hi + off * 4, lo + off * 4, v);
}

// -------------------- routing --------------------
__global__ void k_route(const int* __restrict__ ids) {
    __shared__ int hist[E_NUM];
    int tid = threadIdx.x;
    if (tid < E_NUM) hist[tid] = 0;
    __syncthreads();
    for (int i = tid; i < TK; i += 1024) atomicAdd(&hist[ids[i]], 1);
    __syncthreads();
    if (tid == 0) {
        int off = 0, nt = 0;
        for (int e = 0; e < E_NUM; e++) {
            g_offset[e] = off; g_cursor[e] = 0;
            int c = hist[e];
            for (int r = 0; r < c; r += BM) {
                g_tile_e[nt] = e;
                g_tile_row[nt] = off + r;
                g_tile_rows[nt] = (c - r < BM) ? (c - r) : BM;
                nt++;
            }
            off += c;
        }
        g_num_tiles = nt;
    }
}
__global__ void k_scatter(const int* __restrict__ ids, const float* __restrict__ w) {
    int i = blockIdx.x * blockDim.x + threadIdx.x;
    if (i < TK) {
        int e = ids[i];
        int pos = g_offset[e] + atomicAdd(&g_cursor[e], 1);
        g_pair_token[pos] = i >> 1;
        g_pair_w[pos] = w[i];
        g_pos_of[i] = pos;
    }
}

// ==================== GEMM1: act = silu(X Wg^T) * (X Wu^T) ====================
// grid(8, MAX_TILES), 256 thr (8 warps 2x4), 2 CTAs/SM.
// CTA tile 128 rows x (64 gate + 64 up). Warp tile 64x32. K=1024.
__global__ void __launch_bounds__(256, 2)
k_gemm1(const float* __restrict__ unused) {
    int tile = blockIdx.y;
    if (tile >= g_num_tiles) return;
    const int e = g_tile_e[tile], row0 = g_tile_row[tile], rows = g_tile_rows[tile];
    const int bx = blockIdx.x;

    extern __shared__ __align__(16) char raw[];
    __nv_bfloat16* bsm = (__nv_bfloat16*)raw;
    float* fsm = (float*)raw;
    __shared__ int s_tok[BM];

    const int tid  = threadIdx.x;
    const int warp = tid >> 5;
    const int wm = warp >> 2, wn = warp & 3;

    if (tid < BM) s_tok[tid] = g_pair_token[row0 + ((tid < rows) ? tid : 0)];
    __syncthreads();

    const int row = tid >> 1, half = tid & 1;
    const int grow = (row < 64) ? bx * 64 + row : F_DIM + bx * 64 + (row - 64);
    const __nv_bfloat16* ah = g_hid_hi + (size_t)s_tok[row] * H_DIM + half * 8;
    const __nv_bfloat16* al = g_hid_lo + (size_t)s_tok[row] * H_DIM + half * 8;
    const __nv_bfloat16* wh = g_wgu_hi + ((size_t)e * 2 * F_DIM + grow) * H_DIM + half * 8;
    const __nv_bfloat16* wl = g_wgu_lo + ((size_t)e * 2 * F_DIM + grow) * H_DIM + half * 8;
    const uint32_t sbase = smem_u32(raw) + (uint32_t)(row * PCH + half * 8) * 2;

    FragC acc[4][2];
    #pragma unroll
    for (int i = 0; i < 4; i++)
        #pragma unroll
        for (int j = 0; j < 2; j++) wmma::fill_fragment(acc[i][j], 0.f);

    const int NK = H_DIM / 16;   // 64

    #pragma unroll
    for (int s = 0; s < 2; s++) {
        uint32_t d = sbase + s * STAGE_B;
        int kb = s * 16;
        CP_ASYNC(d,         ah + kb);
        CP_ASYNC(d + 6144,  al + kb);
        CP_ASYNC(d + 12288, wh + kb);
        CP_ASYNC(d + 18432, wl + kb);
        CP_COMMIT();
    }

    for (int kt = 0; kt < NK; kt++) {
        CP_WAIT1();
        __syncthreads();
        if (kt + 2 < NK) {
            int slot = (kt + 2) % 3;
            uint32_t d = sbase + slot * STAGE_B;
            int kb = (kt + 2) * 16;
            CP_ASYNC(d,         ah + kb);
            CP_ASYNC(d + 6144,  al + kb);
            CP_ASYNC(d + 12288, wh + kb);
            CP_ASYNC(d + 18432, wl + kb);
        }
        CP_COMMIT();

        const __nv_bfloat16* st = bsm + (kt % 3) * 12288;
        FragB fbh[2], fbl[2];
        #pragma unroll
        for (int j = 0; j < 2; j++) {
            wmma::load_matrix_sync(fbh[j], st + 6144 + (wn * 32 + j * 16) * PCH, PCH);
            wmma::load_matrix_sync(fbl[j], st + 9216 + (wn * 32 + j * 16) * PCH, PCH);
        }
        #pragma unroll
        for (int i = 0; i < 4; i++) {
            FragA fah, fal;
            wmma::load_matrix_sync(fah, st +        (wm * 64 + i * 16) * PCH, PCH);
            wmma::load_matrix_sync(fal, st + 3072 + (wm * 64 + i * 16) * PCH, PCH);
            #pragma unroll
            for (int j = 0; j < 2; j++) {
                wmma::mma_sync(acc[i][j], fah, fbh[j], acc[i][j]);
                wmma::mma_sync(acc[i][j], fal, fbh[j], acc[i][j]);
                wmma::mma_sync(acc[i][j], fah, fbl[j], acc[i][j]);
            }
        }
    }

    // -------- epilogue: stage gate/up at pitch 68 (64 cols + pad) --------
    __syncthreads();
    float* stg = fsm;               // [128][68] = 8704 floats
    float* stu = fsm + 8704;        // [128][68]; total 69632 B <= 73728 B
    {
        float* dst = (wn < 2) ? stg : stu;
        const int colw = (wn & 1) * 32;
        #pragma unroll
        for (int i = 0; i < 4; i++)
            #pragma unroll
            for (int j = 0; j < 2; j++)
                wmma::store_matrix_sync(dst + (wm * 64 + i * 16) * 68 + colw + j * 16,
                                        acc[i][j], 68, wmma::mem_row_major);
    }
    __syncthreads();
    #pragma unroll
    for (int it = 0; it < 8; it++) {       // 128 rows x 16 float4-chunks
        int q = tid + it * 256;
        int r = q >> 4, c = (q & 15) * 4;
        if (r < rows) {
            float4 o;
            o.x = silu_mul(stg[r*68+c+0], stu[r*68+c+0]);
            o.y = silu_mul(stg[r*68+c+1], stu[r*68+c+1]);
            o.z = silu_mul(stg[r*68+c+2], stu[r*68+c+2]);
            o.w = silu_mul(stg[r*68+c+3], stu[r*68+c+3]);
            size_t oidx = (size_t)(row0 + r) * F_DIM + bx * 64 + c;
            split_store(g_act_hi + oidx, g_act_lo + oidx, o);
        }
    }
}

// ==================== GEMM2: y = coef * (act Wd^T) ====================
// grid(8, MAX_TILES), 256 thr, 2 CTAs/SM. CTA 128x128, K=512.
__global__ void __launch_bounds__(256, 2)
k_gemm2(const float* __restrict__ unused) {
    int tile = blockIdx.y;
    if (tile >= g_num_tiles) return;
    const int e = g_tile_e[tile], row0 = g_tile_row[tile], rows = g_tile_rows[tile];
    const int bx = blockIdx.x;

    extern __shared__ __align__(16) char raw[];
    __nv_bfloat16* bsm = (__nv_bfloat16*)raw;
    float* fsm = (float*)raw;
    __shared__ float s_w[BM];

    const int tid  = threadIdx.x;
    const int warp = tid >> 5;
    const int wm = warp >> 2, wn = warp & 3;

    if (tid < BM) s_w[tid] = g_pair_w[row0 + ((tid < rows) ? tid : 0)];
    __syncthreads();

    const int row = tid >> 1, half = tid & 1;
    const int ar = row0 + ((row < rows) ? row : 0);
    const __nv_bfloat16* ah = g_act_hi + (size_t)ar * F_DIM + half * 8;
    const __nv_bfloat16* al = g_act_lo + (size_t)ar * F_DIM + half * 8;
    const __nv_bfloat16* wh = g_wd_hi + ((size_t)e * H_DIM + bx * 128 + row) * F_DIM + half * 8;
    const __nv_bfloat16* wl = g_wd_lo + ((size_t)e * H_DIM + bx * 128 + row) * F_DIM + half * 8;
    const uint32_t sbase = smem_u32(raw) + (uint32_t)(row * PCH + half * 8) * 2;

    FragC acc[4][2];
    #pragma unroll
    for (int i = 0; i < 4; i++)
        #pragma unroll
        for (int j = 0; j < 2; j++) wmma::fill_fragment(acc[i][j], 0.f);

    const int NK = F_DIM / 16;   // 32

    #pragma unroll
    for (int s = 0; s < 2; s++) {
        uint32_t d = sbase + s * STAGE_B;
        int kb = s * 16;
        CP_ASYNC(d,         ah + kb);
        CP_ASYNC(d + 6144,  al + kb);
        CP_ASYNC(d + 12288, wh + kb);
        CP_ASYNC(d + 18432, wl + kb);
        CP_COMMIT();
    }

    for (int kt = 0; kt < NK; kt++) {
        CP_WAIT1();
        __syncthreads();
        if (kt + 2 < NK) {
            int slot = (kt + 2) % 3;
            uint32_t d = sbase + slot * STAGE_B;
            int kb = (kt + 2) * 16;
            CP_ASYNC(d,         ah + kb);
            CP_ASYNC(d + 6144,  al + kb);
            CP_ASYNC(d + 12288, wh + kb);
            CP_ASYNC(d + 18432, wl + kb);
        }
        CP_COMMIT();

        const __nv_bfloat16* st = bsm + (kt % 3) * 12288;
        FragB fbh[2], fbl[2];
        #pragma unroll
        for (int j = 0; j < 2; j++) {
            wmma::load_matrix_sync(fbh[j], st + 6144 + (wn * 32 + j * 16) * PCH, PCH);
            wmma::load_matrix_sync(fbl[j], st + 9216 + (wn * 32 + j * 16) * PCH, PCH);
        }
        #pragma unroll
        for (int i = 0; i < 4; i++) {
            FragA fah, fal;
            wmma::load_matrix_sync(fah, st +        (wm * 64 + i * 16) * PCH, PCH);
            wmma::load_matrix_sync(fal, st + 3072 + (wm * 64 + i * 16) * PCH, PCH);
            #pragma unroll
            for (int j = 0; j < 2; j++) {
                wmma::mma_sync(acc[i][j], fah, fbh[j], acc[i][j]);
                wmma::mma_sync(acc[i][j], fal, fbh[j], acc[i][j]);
                wmma::mma_sync(acc[i][j], fah, fbl[j], acc[i][j]);
            }
        }
    }

    // -------- epilogue: stage 128x128 (pitch 132), fold coef --------
    __syncthreads();
    float* sty = fsm;   // [128][132] = 67584 B
    #pragma unroll
    for (int i = 0; i < 4; i++)
        #pragma unroll
        for (int j = 0; j < 2; j++)
            wmma::store_matrix_sync(sty + (wm * 64 + i * 16) * 132 + wn * 32 + j * 16,
                                    acc[i][j], 132, wmma::mem_row_major);
    __syncthreads();
    #pragma unroll
    for (int it = 0; it < 16; it++) {      // 128 rows x 32 float4-chunks
        int q = tid + it * 256;
        int r = q >> 5, c = (q & 31) * 4;
        if (r < rows) {
            float coef = s_w[r];
            float4 o;
            o.x = coef * sty[r*132+c+0];
            o.y = coef * sty[r*132+c+1];
            o.z = coef * sty[r*132+c+2];
            o.w = coef * sty[r*132+c+3];
            *(float4*)(g_y + (size_t)(row0 + r) * H_DIM + bx * 128 + c) = o;
        }
    }
}

// -------------------- combine: out[t] = y[pos0] + y[pos1] --------------------
__global__ void k_combine(float* __restrict__ out) {
    int idx = blockIdx.x * 256 + threadIdx.x;
    int t = idx >> 8;
    int c = idx & 255;
    int p0 = g_pos_of[2 * t], p1 = g_pos_of[2 * t + 1];
    const float4* y = (const float4*)g_y;
    float4 a = y[(size_t)p0 * (H_DIM / 4) + c];
    float4 b = y[(size_t)p1 * (H_DIM / 4) + c];
    ((float4*)out)[idx] = make_float4(a.x + b.x, a.y + b.y, a.z + b.z, a.w + b.w);
}

// -------------------- launch --------------------
extern "C" void kernel_launch(void* const* d_in, const int* in_sizes, int n_in,
                              void* d_out, int out_size) {
    const float* hidden   = (const float*)d_in[0];
    const float* topk_w   = (const float*)d_in[1];
    const int*   topk_ids = (const int*)d_in[2];
    const float* w_gu     = (const float*)d_in[3];
    const float* w_d      = (const float*)d_in[4];
    float* out = (float*)d_out;

    cudaFuncSetAttribute(k_gemm1, cudaFuncAttributeMaxDynamicSharedMemorySize, SMEM_BYTES);
    cudaFuncSetAttribute(k_gemm2, cudaFuncAttributeMaxDynamicSharedMemorySize, SMEM_BYTES);

    k_split_all<<<N4_ALL / 256, 256>>>(hidden, w_gu, w_d);          // launch 1
    k_route<<<1, 1024>>>(topk_ids);                                 // launch 2
    k_scatter<<<TK / 256, 256>>>(topk_ids, topk_w);                 // launch 3
    k_gemm1<<<dim3(8, MAX_TILES), 256, SMEM_BYTES>>>(hidden);       // launch 4 (ncu slot)
    k_gemm2<<<dim3(8, MAX_TILES), 256, SMEM_BYTES>>>(w_d);          // launch 5
    k_combine<<<(T_TOK * H_DIM / 4) / 256, 256>>>(out);             // launch 6
}

// round 11
// speedup vs baseline: 2.5648x; 1.5191x over previous
#include <cuda_runtime.h>
#include <cstdint>
#include <math.h>

#define T_TOK 16384
#define H_DIM 1024
#define F_DIM 512
#define E_NUM 64
#define TK    (T_TOK * 2)            // 32768 routed pairs
#define BM    128
#define MAX_TILES (TK / BM + E_NUM)  // 320
#define PCH   20                     // f32 smem pitch: 80B rows -> conflict-free LDSM

// rounding-pass ranges (float4 units)
#define N4_HID (T_TOK * H_DIM / 4)
#define N4_WGU (E_NUM * 2 * F_DIM * H_DIM / 4)
#define N4_WD  (E_NUM * H_DIM * F_DIM / 4)
#define N4_ALL (N4_HID + N4_WGU + N4_WD)

// -------------------- static device scratch --------------------
__device__ int   g_offset[E_NUM];
__device__ int   g_cursor[E_NUM];
__device__ int   g_pair_token[TK];
__device__ float g_pair_w[TK];
__device__ int   g_pos_of[TK];
__device__ int   g_num_tiles;
__device__ int   g_tile_e[MAX_TILES];
__device__ int   g_tile_row[MAX_TILES];
__device__ int   g_tile_rows[MAX_TILES];

__device__ __align__(16) float g_hid[(size_t)T_TOK * H_DIM];            // tf32-rounded
__device__ __align__(16) float g_wgu[(size_t)E_NUM * 2 * F_DIM * H_DIM];
__device__ __align__(16) float g_wd [(size_t)E_NUM * H_DIM * F_DIM];
__device__ __align__(16) float g_act[(size_t)TK * F_DIM];               // tf32-rounded
__device__ __align__(16) float g_y  [(size_t)TK * H_DIM];

// -------------------- helpers --------------------
__device__ __forceinline__ float t32(float x) {
    uint32_t u;
    asm("cvt.rna.tf32.f32 %0, %1;" : "=r"(u) : "f"(x));
    return __uint_as_float(u);
}
__device__ __forceinline__ float silu_mul(float g, float u) {
    return g / (1.f + __expf(-g)) * u;
}
__device__ __forceinline__ uint32_t smem_u32(const void* p) {
    uint32_t a;
    asm("{ .reg .u64 t; cvta.to.shared.u64 t, %1; cvt.u32.u64 %0, t; }" : "=r"(a) : "l"(p));
    return a;
}

#define CP_ASYNC(dst, src) \
    asm volatile("cp.async.cg.shared.global [%0], [%1], 16;" :: "r"(dst), "l"(src))
#define CP_COMMIT() asm volatile("cp.async.commit_group;" ::: "memory")
#define CP_WAIT2()  asm volatile("cp.async.wait_group 2;" ::: "memory")
#define CP_WAIT0()  asm volatile("cp.async.wait_group 0;" ::: "memory")

#define LDSM4(r0, r1, r2, r3, addr) \
    asm volatile("ldmatrix.sync.aligned.m8n8.x4.shared.b16 {%0,%1,%2,%3}, [%4];" \
        : "=r"(r0), "=r"(r1), "=r"(r2), "=r"(r3) : "r"(addr))

#define MMA_TF32(c, a0, a1, a2, a3, b0, b1) \
    asm volatile("mma.sync.aligned.m16n8k8.row.col.f32.tf32.tf32.f32 " \
        "{%0,%1,%2,%3}, {%4,%5,%6,%7}, {%8,%9}, {%0,%1,%2,%3};" \
        : "+f"((c)[0]), "+f"((c)[1]), "+f"((c)[2]), "+f"((c)[3]) \
        : "r"(a0), "r"(a1), "r"(a2), "r"(a3), "r"(b0), "r"(b1))

// stage layout (f32): A [128][PCH] @ 0 ; W [128][PCH] @ 2560. Stage 20480 B x 4.
#define STG_BYTES 20480
#define SMEM_BYTES 81920

// -------------------- tf32 rounding pass --------------------
__global__ void k_round_all(const float* __restrict__ hidden,
                            const float* __restrict__ wgu,
                            const float* __restrict__ wd) {
    size_t i = (size_t)blockIdx.x * 256 + threadIdx.x;
    const float4* src;
    float* dst;
    size_t off;
    if (i < N4_HID)               { src = (const float4*)hidden; dst = g_hid; off = i; }
    else if (i < N4_HID + N4_WGU) { src = (const float4*)wgu;    dst = g_wgu; off = i - N4_HID; }
    else                          { src = (const float4*)wd;     dst = g_wd;  off = i - N4_HID - N4_WGU; }
    float4 v = src[off];
    float4 o = make_float4(t32(v.x), t32(v.y), t32(v.z), t32(v.w));
    *(float4*)(dst + off * 4) = o;
}

// -------------------- routing --------------------
__global__ void k_route(const int* __restrict__ ids) {
    __shared__ int hist[E_NUM];
    int tid = threadIdx.x;
    if (tid < E_NUM) hist[tid] = 0;
    __syncthreads();
    for (int i = tid; i < TK; i += 1024) atomicAdd(&hist[ids[i]], 1);
    __syncthreads();
    if (tid == 0) {
        int off = 0, nt = 0;
        for (int e = 0; e < E_NUM; e++) {
            g_offset[e] = off; g_cursor[e] = 0;
            int c = hist[e];
            for (int r = 0; r < c; r += BM) {
                g_tile_e[nt] = e;
                g_tile_row[nt] = off + r;
                g_tile_rows[nt] = (c - r < BM) ? (c - r) : BM;
                nt++;
            }
            off += c;
        }
        g_num_tiles = nt;
    }
}
__global__ void k_scatter(const int* __restrict__ ids, const float* __restrict__ w) {
    int i = blockIdx.x * blockDim.x + threadIdx.x;
    if (i < TK) {
        int e = ids[i];
        int pos = g_offset[e] + atomicAdd(&g_cursor[e], 1);
        g_pair_token[pos] = i >> 1;
        g_pair_w[pos] = w[i];
        g_pos_of[i] = pos;
    }
}

// ==================== GEMM1: act = silu(X Wg^T) * (X Wu^T) ====================
// grid(8, MAX_TILES), 256 thr (8 warps 2x4), 2 CTAs/SM.
// CTA 128 rows x (64 gate + 64 up). Warp tile 64x32 (tf32 m16n8k8). K=1024.
__global__ void __launch_bounds__(256, 2)
k_gemm1(const float* __restrict__ unused) {
    int tile = blockIdx.y;
    if (tile >= g_num_tiles) return;
    const int e = g_tile_e[tile], row0 = g_tile_row[tile], rows = g_tile_rows[tile];
    const int bx = blockIdx.x;

    extern __shared__ __align__(16) float fsm[];
    __shared__ int s_tok[BM];

    const int tid  = threadIdx.x;
    const int warp = tid >> 5, lane = tid & 31;
    const int wm = warp >> 2, wn = warp & 3;

    if (tid < BM) s_tok[tid] = g_pair_token[row0 + ((tid < rows) ? tid : 0)];
    __syncthreads();

    // ---- cp.async mapping: per thread 4 chunks (A r, A r+64, W gate r, W up r)
    const int arw = tid >> 2, c4 = (tid & 3) * 4;       // arw in 0..63
    const int grow0 = bx * 64 + arw;                    // gate row -> smem W row arw
    const int grow1 = F_DIM + bx * 64 + arw;            // up row   -> smem W row arw+64
    const float* pA0 = g_hid + (size_t)s_tok[arw] * H_DIM + c4;
    const float* pA1 = g_hid + (size_t)s_tok[arw + 64] * H_DIM + c4;
    const float* pW0 = g_wgu + ((size_t)e * 2 * F_DIM + grow0) * H_DIM + c4;
    const float* pW1 = g_wgu + ((size_t)e * 2 * F_DIM + grow1) * H_DIM + c4;
    const uint32_t s0 = smem_u32(fsm);
    const uint32_t dA0 = s0 + (uint32_t)(arw * PCH + c4) * 4;
    const uint32_t dA1 = dA0 + 64 * PCH * 4;
    const uint32_t dW0 = dA0 + 128 * PCH * 4;
    const uint32_t dW1 = dW0 + 64 * PCH * 4;

    // ---- ldmatrix lane addressing
    const int arow_l = (lane & 7) + ((lane >> 3) & 1) * 8;
    const int acol_l = ((lane >> 4) & 1) * 4;
    const uint32_t aA = s0 + (uint32_t)((wm * 64 + arow_l) * PCH + acol_l) * 4;
    const uint32_t aB = s0 + 128 * PCH * 4 + (uint32_t)((wn * 32 + arow_l) * PCH + acol_l) * 4;

    float acc[4][4][4];
    #pragma unroll
    for (int i = 0; i < 4; i++)
        #pragma unroll
        for (int j = 0; j < 4; j++)
            #pragma unroll
            for (int q = 0; q < 4; q++) acc[i][j][q] = 0.f;

    const int NK = H_DIM / 16;   // 64

    #pragma unroll
    for (int s = 0; s < 3; s++) {
        uint32_t so = s * STG_BYTES;
        int kb = s * 16;
        CP_ASYNC(dA0 + so, pA0 + kb);
        CP_ASYNC(dA1 + so, pA1 + kb);
        CP_ASYNC(dW0 + so, pW0 + kb);
        CP_ASYNC(dW1 + so, pW1 + kb);
        CP_COMMIT();
    }

    for (int kt = 0; kt < NK; kt++) {
        CP_WAIT2();
        __syncthreads();
        if (kt + 3 < NK) {
            uint32_t so = ((kt + 3) & 3) * STG_BYTES;
            int kb = (kt + 3) * 16;
            CP_ASYNC(dA0 + so, pA0 + kb);
            CP_ASYNC(dA1 + so, pA1 + kb);
            CP_ASYNC(dW0 + so, pW0 + kb);
            CP_ASYNC(dW1 + so, pW1 + kb);
        }
        CP_COMMIT();

        const uint32_t so = (kt & 3) * STG_BYTES;
        const uint32_t A0 = aA + so, B0 = aB + so;
        #pragma unroll
        for (int k8 = 0; k8 < 2; k8++) {
            // ldsm x4 on B returns: b0=(n0-7,k0-3) b1=(n8-15,k0-3) b2=(n0-7,k4-7) b3=(n8-15,k4-7)
            uint32_t b0, b1, b2, b3, b4, b5, b6, b7;
            LDSM4(b0, b1, b2, b3, B0 + k8 * 32);
            LDSM4(b4, b5, b6, b7, B0 + 16 * PCH * 4 + k8 * 32);
            #pragma unroll
            for (int i = 0; i < 4; i++) {
                uint32_t a0, a1, a2, a3;
                LDSM4(a0, a1, a2, a3, A0 + i * 16 * PCH * 4 + k8 * 32);
                // mma B operands: (k0-3 half, k4-7 half) of the SAME n-block
                MMA_TF32(acc[i][0], a0, a1, a2, a3, b0, b2);
                MMA_TF32(acc[i][1], a0, a1, a2, a3, b1, b3);
                MMA_TF32(acc[i][2], a0, a1, a2, a3, b4, b6);
                MMA_TF32(acc[i][3], a0, a1, a2, a3, b5, b7);
            }
        }
    }
    CP_WAIT0();

    // -------- epilogue: stage gate/up at pitch 68 --------
    __syncthreads();
    float* stg = fsm;               // [128][68]
    float* stu = fsm + 8704;        // [128][68]; 69632 B <= 81920 B
    {
        float* dst = (wn < 2) ? stg : stu;
        const int lcb = (wn & 1) * 32;
        const int g = lane >> 2, tg = lane & 3;
        #pragma unroll
        for (int i = 0; i < 4; i++) {
            int r = wm * 64 + i * 16 + g;
            #pragma unroll
            for (int j = 0; j < 4; j++) {
                int cc = lcb + j * 8 + tg * 2;
                *(float2*)&dst[r * 68 + cc]       = make_float2(acc[i][j][0], acc[i][j][1]);
                *(float2*)&dst[(r + 8) * 68 + cc] = make_float2(acc[i][j][2], acc[i][j][3]);
            }
        }
    }
    __syncthreads();
    #pragma unroll
    for (int it = 0; it < 8; it++) {       // 128 rows x 16 float4-chunks
        int q = tid + it * 256;
        int r = q >> 4, c = (q & 15) * 4;
        if (r < rows) {
            float4 o;
            o.x = t32(silu_mul(stg[r*68+c+0], stu[r*68+c+0]));
            o.y = t32(silu_mul(stg[r*68+c+1], stu[r*68+c+1]));
            o.z = t32(silu_mul(stg[r*68+c+2], stu[r*68+c+2]));
            o.w = t32(silu_mul(stg[r*68+c+3], stu[r*68+c+3]));
            *(float4*)(g_act + (size_t)(row0 + r) * F_DIM + bx * 64 + c) = o;
        }
    }
}

// ==================== GEMM2: y = coef * (act Wd^T) ====================
// grid(8, MAX_TILES), 256 thr, 2 CTAs/SM. CTA 128x128, K=512.
__global__ void __launch_bounds__(256, 2)
k_gemm2(const float* __restrict__ unused) {
    int tile = blockIdx.y;
    if (tile >= g_num_tiles) return;
    const int e = g_tile_e[tile], row0 = g_tile_row[tile], rows = g_tile_rows[tile];
    const int bx = blockIdx.x;

    extern __shared__ __align__(16) float fsm[];
    __shared__ float s_w[BM];

    const int tid  = threadIdx.x;
    const int warp = tid >> 5, lane = tid & 31;
    const int wm = warp >> 2, wn = warp & 3;

    if (tid < BM) s_w[tid] = g_pair_w[row0 + ((tid < rows) ? tid : 0)];
    __syncthreads();

    const int arw = tid >> 2, c4 = (tid & 3) * 4;
    const int ar0 = row0 + ((arw < rows) ? arw : 0);
    const int ar1 = row0 + ((arw + 64 < rows) ? arw + 64 : 0);
    const float* pA0 = g_act + (size_t)ar0 * F_DIM + c4;
    const float* pA1 = g_act + (size_t)ar1 * F_DIM + c4;
    const float* pW0 = g_wd + ((size_t)e * H_DIM + bx * 128 + arw) * F_DIM + c4;
    const float* pW1 = pW0 + (size_t)64 * F_DIM;
    const uint32_t s0 = smem_u32(fsm);
    const uint32_t dA0 = s0 + (uint32_t)(arw * PCH + c4) * 4;
    const uint32_t dA1 = dA0 + 64 * PCH * 4;
    const uint32_t dW0 = dA0 + 128 * PCH * 4;
    const uint32_t dW1 = dW0 + 64 * PCH * 4;

    const int arow_l = (lane & 7) + ((lane >> 3) & 1) * 8;
    const int acol_l = ((lane >> 4) & 1) * 4;
    const uint32_t aA = s0 + (uint32_t)((wm * 64 + arow_l) * PCH + acol_l) * 4;
    const uint32_t aB = s0 + 128 * PCH * 4 + (uint32_t)((wn * 32 + arow_l) * PCH + acol_l) * 4;

    float acc[4][4][4];
    #pragma unroll
    for (int i = 0; i < 4; i++)
        #pragma unroll
        for (int j = 0; j < 4; j++)
            #pragma unroll
            for (int q = 0; q < 4; q++) acc[i][j][q] = 0.f;

    const int NK = F_DIM / 16;   // 32

    #pragma unroll
    for (int s = 0; s < 3; s++) {
        uint32_t so = s * STG_BYTES;
        int kb = s * 16;
        CP_ASYNC(dA0 + so, pA0 + kb);
        CP_ASYNC(dA1 + so, pA1 + kb);
        CP_ASYNC(dW0 + so, pW0 + kb);
        CP_ASYNC(dW1 + so, pW1 + kb);
        CP_COMMIT();
    }

    for (int kt = 0; kt < NK; kt++) {
        CP_WAIT2();
        __syncthreads();
        if (kt + 3 < NK) {
            uint32_t so = ((kt + 3) & 3) * STG_BYTES;
            int kb = (kt + 3) * 16;
            CP_ASYNC(dA0 + so, pA0 + kb);
            CP_ASYNC(dA1 + so, pA1 + kb);
            CP_ASYNC(dW0 + so, pW0 + kb);
            CP_ASYNC(dW1 + so, pW1 + kb);
        }
        CP_COMMIT();

        const uint32_t so = (kt & 3) * STG_BYTES;
        const uint32_t A0 = aA + so, B0 = aB + so;
        #pragma unroll
        for (int k8 = 0; k8 < 2; k8++) {
            uint32_t b0, b1, b2, b3, b4, b5, b6, b7;
            LDSM4(b0, b1, b2, b3, B0 + k8 * 32);
            LDSM4(b4, b5, b6, b7, B0 + 16 * PCH * 4 + k8 * 32);
            #pragma unroll
            for (int i = 0; i < 4; i++) {
                uint32_t a0, a1, a2, a3;
                LDSM4(a0, a1, a2, a3, A0 + i * 16 * PCH * 4 + k8 * 32);
                MMA_TF32(acc[i][0], a0, a1, a2, a3, b0, b2);
                MMA_TF32(acc[i][1], a0, a1, a2, a3, b1, b3);
                MMA_TF32(acc[i][2], a0, a1, a2, a3, b4, b6);
                MMA_TF32(acc[i][3], a0, a1, a2, a3, b5, b7);
            }
        }
    }
    CP_WAIT0();

    // -------- epilogue: stage 128x128 (pitch 132), fold coef --------
    __syncthreads();
    float* sty = fsm;   // [128][132] = 67584 B
    {
        const int g = lane >> 2, tg = lane & 3;
        #pragma unroll
        for (int i = 0; i < 4; i++) {
            int r = wm * 64 + i * 16 + g;
            #pragma unroll
            for (int j = 0; j < 4; j++) {
                int cc = wn * 32 + j * 8 + tg * 2;
                *(float2*)&sty[r * 132 + cc]       = make_float2(acc[i][j][0], acc[i][j][1]);
                *(float2*)&sty[(r + 8) * 132 + cc] = make_float2(acc[i][j][2], acc[i][j][3]);
            }
        }
    }
    __syncthreads();
    #pragma unroll
    for (int it = 0; it < 16; it++) {      // 128 rows x 32 float4-chunks
        int q = tid + it * 256;
        int r = q >> 5, c = (q & 31) * 4;
        if (r < rows) {
            float coef = s_w[r];
            float4 o;
            o.x = coef * sty[r*132+c+0];
            o.y = coef * sty[r*132+c+1];
            o.z = coef * sty[r*132+c+2];
            o.w = coef * sty[r*132+c+3];
            *(float4*)(g_y + (size_t)(row0 + r) * H_DIM + bx * 128 + c) = o;
        }
    }
}

// -------------------- combine: out[t] = y[pos0] + y[pos1] --------------------
__global__ void k_combine(float* __restrict__ out) {
    int idx = blockIdx.x * 256 + threadIdx.x;
    int t = idx >> 8;
    int c = idx & 255;
    int p0 = g_pos_of[2 * t], p1 = g_pos_of[2 * t + 1];
    const float4* y = (const float4*)g_y;
    float4 a = y[(size_t)p0 * (H_DIM / 4) + c];
    float4 b = y[(size_t)p1 * (H_DIM / 4) + c];
    ((float4*)out)[idx] = make_float4(a.x + b.x, a.y + b.y, a.z + b.z, a.w + b.w);
}

// -------------------- launch --------------------
extern "C" void kernel_launch(void* const* d_in, const int* in_sizes, int n_in,
                              void* d_out, int out_size) {
    const float* hidden   = (const float*)d_in[0];
    const float* topk_w   = (const float*)d_in[1];
    const int*   topk_ids = (const int*)d_in[2];
    const float* w_gu     = (const float*)d_in[3];
    const float* w_d      = (const float*)d_in[4];
    float* out = (float*)d_out;

    cudaFuncSetAttribute(k_gemm1, cudaFuncAttributeMaxDynamicSharedMemorySize, SMEM_BYTES);
    cudaFuncSetAttribute(k_gemm2, cudaFuncAttributeMaxDynamicSharedMemorySize, SMEM_BYTES);

    k_round_all<<<N4_ALL / 256, 256>>>(hidden, w_gu, w_d);          // launch 1
    k_route<<<1, 1024>>>(topk_ids);                                 // launch 2
    k_scatter<<<TK / 256, 256>>>(topk_ids, topk_w);                 // launch 3
    k_gemm1<<<dim3(8, MAX_TILES), 256, SMEM_BYTES>>>(hidden);       // launch 4 (ncu slot)
    k_gemm2<<<dim3(8, MAX_TILES), 256, SMEM_BYTES>>>(w_d);          // launch 5
    k_combine<<<(T_TOK * H_DIM / 4) / 256, 256>>>(out);             // launch 6
}